// round 14
// baseline (speedup 1.0000x reference)
#include <cuda_runtime.h>
#include <cuda_bf16.h>
#include <cstdint>
#include <math.h>

#define BB 16
#define CC 512
#define HW 4096
#define KK 64
#define SPLIT 8

// ---------------------------------------------------------------------------
// Scratch
// ---------------------------------------------------------------------------
__device__ float g_buf1[BB * CC * HW];
__device__ float g_z[BB * HW * KK];
__device__ float g_mu[BB * CC * KK];
__device__ float g_mu_part[BB * SPLIT * CC * KK]; // mstep partials; BN partials
__device__ float g_scale[CC];
__device__ float g_shift[CC];

__device__ __nv_bfloat16 g_w1hi[CC * CC], g_w1lo[CC * CC];
__device__ __nv_bfloat16 g_w2hi[CC * CC], g_w2lo[CC * CC];
__device__ __nv_bfloat16 g_xhi[BB * CC * HW],  g_xlo[BB * CC * HW];
__device__ __nv_bfloat16 g_xfhi[BB * CC * HW], g_xflo[BB * CC * HW];
__device__ __nv_bfloat16 g_xrhi[BB * CC * HW], g_xrlo[BB * CC * HW];
__device__ __nv_bfloat16 g_zhi[BB * HW * KK],  g_zlo[BB * HW * KK];
__device__ __nv_bfloat16 g_muhi[BB * CC * KK], g_mulo[BB * CC * KK];

#define BN_SLOTS 2048   // 16 b * 16 n-tiles * 8 wn-groups

// ---------------------------------------------------------------------------
// PTX helpers
// ---------------------------------------------------------------------------
__device__ __forceinline__ uint32_t smem_u32(const void* p) {
    return (uint32_t)__cvta_generic_to_shared(p);
}
__device__ __forceinline__ void cp_async16(uint32_t saddr, const void* gaddr) {
    asm volatile("cp.async.cg.shared.global [%0], [%1], 16;" :: "r"(saddr), "l"(gaddr));
}
__device__ __forceinline__ void ldsm_x4(uint32_t& r0, uint32_t& r1, uint32_t& r2, uint32_t& r3, uint32_t a) {
    asm volatile("ldmatrix.sync.aligned.m8n8.x4.shared.b16 {%0,%1,%2,%3}, [%4];"
                 : "=r"(r0), "=r"(r1), "=r"(r2), "=r"(r3) : "r"(a));
}
__device__ __forceinline__ void ldsm_x4_t(uint32_t& r0, uint32_t& r1, uint32_t& r2, uint32_t& r3, uint32_t a) {
    asm volatile("ldmatrix.sync.aligned.m8n8.x4.trans.shared.b16 {%0,%1,%2,%3}, [%4];"
                 : "=r"(r0), "=r"(r1), "=r"(r2), "=r"(r3) : "r"(a));
}
__device__ __forceinline__ void mma_bf16(float* c, const uint32_t* a, uint32_t b0, uint32_t b1) {
    asm volatile("mma.sync.aligned.m16n8k16.row.col.f32.bf16.bf16.f32 "
                 "{%0,%1,%2,%3}, {%4,%5,%6,%7}, {%8,%9}, {%0,%1,%2,%3};"
                 : "+f"(c[0]), "+f"(c[1]), "+f"(c[2]), "+f"(c[3])
                 : "r"(a[0]), "r"(a[1]), "r"(a[2]), "r"(a[3]), "r"(b0), "r"(b1));
}
__device__ __forceinline__ void split_val(float v, __nv_bfloat16& h, __nv_bfloat16& l) {
    h = __float2bfloat16(v);
    l = __float2bfloat16(v - __bfloat162float(h));
}

// ---------------------------------------------------------------------------
// Conversions
// ---------------------------------------------------------------------------
__global__ void split_w_kernel(const float* __restrict__ w1, const float* __restrict__ w2) {
    int i = blockIdx.x * 256 + threadIdx.x;
    split_val(w1[i], g_w1hi[i], g_w1lo[i]);
    split_val(w2[i], g_w2hi[i], g_w2lo[i]);
}
__global__ void split_x_kernel(const float* __restrict__ x) {
    size_t i = ((size_t)blockIdx.x * 256 + threadIdx.x) * 4;
    float4 v = *reinterpret_cast<const float4*>(&x[i]);
    __nv_bfloat16 h0, h1, h2, h3, l0, l1, l2, l3;
    split_val(v.x, h0, l0); split_val(v.y, h1, l1);
    split_val(v.z, h2, l2); split_val(v.w, h3, l3);
    *reinterpret_cast<__nv_bfloat162*>(&g_xhi[i])     = __nv_bfloat162{h0, h1};
    *reinterpret_cast<__nv_bfloat162*>(&g_xhi[i + 2]) = __nv_bfloat162{h2, h3};
    *reinterpret_cast<__nv_bfloat162*>(&g_xlo[i])     = __nv_bfloat162{l0, l1};
    *reinterpret_cast<__nv_bfloat162*>(&g_xlo[i + 2]) = __nv_bfloat162{l2, l3};
}
__global__ void copymu_kernel(const float* __restrict__ mu_in) {
    int b = blockIdx.y;
    int i = blockIdx.x * 256 + threadIdx.x;
    __nv_bfloat16 h, l; split_val(mu_in[i], h, l);
    size_t idx = (size_t)b * CC * KK + i;
    g_muhi[idx] = h; g_mulo[idx] = l;
}

// ---------------------------------------------------------------------------
// conv GEMM: M=128 x N=256 tiles, 512 threads (16 warps: 2m x 8n), 1 CTA/SM.
// Fused split-bf16 3-term; conv2 emits BN partials.
// ---------------------------------------------------------------------------
#define APITCH 40
#define BPN 264
#define CSTG_A (128 * APITCH * 2)   // 10240
#define CSTG_B (32 * BPN * 2)       // 16896
#define CONV_SMEM (4 * CSTG_A + 4 * CSTG_B)   // 108544

__global__ __launch_bounds__(512) void conv_mma_kernel(const float* __restrict__ bias, int sel) {
    extern __shared__ __align__(16) char csm[];
    const int b  = blockIdx.z;
    const int m0 = blockIdx.y * 128;
    const int n0 = blockIdx.x * 256;
    const int tid  = threadIdx.x;
    const int lane = tid & 31;
    const int wid  = tid >> 5;
    const int wm   = (wid & 1) * 64;
    const int wn   = (wid >> 1) * 32;

    const uint32_t base = smem_u32(csm);
    const uint32_t oAH = 0, oAL = 2 * CSTG_A;
    const uint32_t oBH = 4 * CSTG_A, oBL = 4 * CSTG_A + 2 * CSTG_B;

    const __nv_bfloat16* Whi = sel ? g_w2hi : g_w1hi;
    const __nv_bfloat16* Wlo = sel ? g_w2lo : g_w1lo;
    const __nv_bfloat16* Xhi = (sel ? g_xrhi : g_xhi) + (size_t)b * CC * HW;
    const __nv_bfloat16* Xlo = (sel ? g_xrlo : g_xlo) + (size_t)b * CC * HW;

    float acc[4][4][4];
#pragma unroll
    for (int i = 0; i < 4; i++)
#pragma unroll
        for (int j = 0; j < 4; j++)
#pragma unroll
            for (int q = 0; q < 4; q++) acc[i][j][q] = 0.f;

    const int ar0 = tid >> 2, ac0 = (tid & 3) * 8;   // A: 512 chunks, 1/thread

    const int NT = 16;

#define LOAD_TILE(IT, BUF) do {                                                   \
        int k0 = (IT) * 32;                                                       \
        uint32_t aH = base + oAH + (BUF) * CSTG_A, aL = base + oAL + (BUF) * CSTG_A; \
        uint32_t bH = base + oBH + (BUF) * CSTG_B, bL = base + oBL + (BUF) * CSTG_B; \
        cp_async16(aH + (ar0 * APITCH + ac0) * 2, Whi + (size_t)(m0 + ar0) * CC + k0 + ac0); \
        cp_async16(aL + (ar0 * APITCH + ac0) * 2, Wlo + (size_t)(m0 + ar0) * CC + k0 + ac0); \
        _Pragma("unroll")                                                          \
        for (int t = 0; t < 2; t++) {                                             \
            int idx = tid + t * 512, r = idx >> 5, c = (idx & 31) * 8;            \
            cp_async16(bH + (r * BPN + c) * 2, Xhi + (size_t)(k0 + r) * HW + n0 + c); \
            cp_async16(bL + (r * BPN + c) * 2, Xlo + (size_t)(k0 + r) * HW + n0 + c); \
        }                                                                          \
        asm volatile("cp.async.commit_group;");                                   \
    } while (0)

    LOAD_TILE(0, 0);
    for (int it = 0; it < NT; ++it) {
        if (it + 1 < NT) { LOAD_TILE(it + 1, (it + 1) & 1); asm volatile("cp.async.wait_group 1;"); }
        else             { asm volatile("cp.async.wait_group 0;"); }
        __syncthreads();

        const int buf = it & 1;
        const uint32_t aH = base + oAH + buf * CSTG_A, aL = base + oAL + buf * CSTG_A;
        const uint32_t bH = base + oBH + buf * CSTG_B, bL = base + oBL + buf * CSTG_B;
#pragma unroll
        for (int kk = 0; kk < 32; kk += 16) {
            uint32_t ah[4][4], al[4][4], bh[2][4], bl[2][4];
#pragma unroll
            for (int im = 0; im < 4; im++) {
                uint32_t off = (((wm + im * 16 + (lane & 15)) * APITCH) + kk + ((lane >> 4) << 3)) * 2;
                ldsm_x4(ah[im][0], ah[im][1], ah[im][2], ah[im][3], aH + off);
                ldsm_x4(al[im][0], al[im][1], al[im][2], al[im][3], aL + off);
            }
#pragma unroll
            for (int jn = 0; jn < 2; jn++) {
                uint32_t off = (((kk + (lane & 7) + ((lane >> 3) & 1) * 8) * BPN)
                                + wn + jn * 16 + ((lane >> 4) << 3)) * 2;
                ldsm_x4_t(bh[jn][0], bh[jn][1], bh[jn][2], bh[jn][3], bH + off);
                ldsm_x4_t(bl[jn][0], bl[jn][1], bl[jn][2], bl[jn][3], bL + off);
            }
#pragma unroll
            for (int im = 0; im < 4; im++)
#pragma unroll
                for (int jn = 0; jn < 2; jn++) {
                    mma_bf16(acc[im][jn * 2 + 0], ah[im], bh[jn][0], bh[jn][1]);
                    mma_bf16(acc[im][jn * 2 + 1], ah[im], bh[jn][2], bh[jn][3]);
                }
#pragma unroll
            for (int im = 0; im < 4; im++)
#pragma unroll
                for (int jn = 0; jn < 2; jn++) {
                    mma_bf16(acc[im][jn * 2 + 0], al[im], bh[jn][0], bh[jn][1]);
                    mma_bf16(acc[im][jn * 2 + 1], al[im], bh[jn][2], bh[jn][3]);
                }
#pragma unroll
            for (int im = 0; im < 4; im++)
#pragma unroll
                for (int jn = 0; jn < 2; jn++) {
                    mma_bf16(acc[im][jn * 2 + 0], ah[im], bl[jn][0], bl[jn][1]);
                    mma_bf16(acc[im][jn * 2 + 1], ah[im], bl[jn][2], bl[jn][3]);
                }
        }
        __syncthreads();
    }
#undef LOAD_TILE

    if (sel == 0) {
        __nv_bfloat16* Oh = g_xfhi + (size_t)b * CC * HW;
        __nv_bfloat16* Ol = g_xflo + (size_t)b * CC * HW;
#pragma unroll
        for (int im = 0; im < 4; im++) {
            int row = m0 + wm + im * 16 + (lane >> 2);
            float bv0 = bias[row], bv1 = bias[row + 8];
#pragma unroll
            for (int j8 = 0; j8 < 4; j8++) {
                int col = n0 + wn + j8 * 8 + (lane & 3) * 2;
                __nv_bfloat16 h0, h1, h2, h3, l0, l1, l2, l3;
                split_val(acc[im][j8][0] + bv0, h0, l0);
                split_val(acc[im][j8][1] + bv0, h1, l1);
                split_val(acc[im][j8][2] + bv1, h2, l2);
                split_val(acc[im][j8][3] + bv1, h3, l3);
                *reinterpret_cast<__nv_bfloat162*>(&Oh[(size_t)row * HW + col]) = __nv_bfloat162{h0, h1};
                *reinterpret_cast<__nv_bfloat162*>(&Ol[(size_t)row * HW + col]) = __nv_bfloat162{l0, l1};
                *reinterpret_cast<__nv_bfloat162*>(&Oh[(size_t)(row + 8) * HW + col]) = __nv_bfloat162{h2, h3};
                *reinterpret_cast<__nv_bfloat162*>(&Ol[(size_t)(row + 8) * HW + col]) = __nv_bfloat162{l2, l3};
            }
        }
    } else {
        float* Yb = g_buf1 + (size_t)b * CC * HW;
        float* psum = g_mu_part;
        float* psq  = g_mu_part + (size_t)BN_SLOTS * CC;
        const int slot = ((b * 16 + blockIdx.x) * 8) + (wid >> 1);
#pragma unroll
        for (int im = 0; im < 4; im++) {
            int row = m0 + wm + im * 16 + (lane >> 2);
            float s0 = 0.f, q0 = 0.f, s1 = 0.f, q1 = 0.f;
#pragma unroll
            for (int j8 = 0; j8 < 4; j8++) {
                int col = n0 + wn + j8 * 8 + (lane & 3) * 2;
                float a0 = acc[im][j8][0], a1 = acc[im][j8][1];
                float a2 = acc[im][j8][2], a3 = acc[im][j8][3];
                *reinterpret_cast<float2*>(&Yb[(size_t)row * HW + col]) = {a0, a1};
                *reinterpret_cast<float2*>(&Yb[(size_t)(row + 8) * HW + col]) = {a2, a3};
                s0 += a0 + a1; q0 = fmaf(a0, a0, fmaf(a1, a1, q0));
                s1 += a2 + a3; q1 = fmaf(a2, a2, fmaf(a3, a3, q1));
            }
            s0 += __shfl_xor_sync(0xffffffffu, s0, 1); s0 += __shfl_xor_sync(0xffffffffu, s0, 2);
            q0 += __shfl_xor_sync(0xffffffffu, q0, 1); q0 += __shfl_xor_sync(0xffffffffu, q0, 2);
            s1 += __shfl_xor_sync(0xffffffffu, s1, 1); s1 += __shfl_xor_sync(0xffffffffu, s1, 2);
            q1 += __shfl_xor_sync(0xffffffffu, q1, 1); q1 += __shfl_xor_sync(0xffffffffu, q1, 2);
            if ((lane & 3) == 0) {
                psum[(size_t)slot * CC + row]     = s0;
                psq [(size_t)slot * CC + row]     = q0;
                psum[(size_t)slot * CC + row + 8] = s1;
                psq [(size_t)slot * CC + row + 8] = q1;
            }
        }
    }
}

// ---------------------------------------------------------------------------
// BN finalize
// ---------------------------------------------------------------------------
__global__ void bn_final_kernel(const float* __restrict__ gamma,
                                const float* __restrict__ beta) {
    const int o = blockIdx.x;
    const int tid = threadIdx.x;
    const float* psum = g_mu_part;
    const float* psq  = g_mu_part + (size_t)BN_SLOTS * CC;
    float s = 0.f, q = 0.f;
    for (int i = tid; i < BN_SLOTS; i += 256) {
        s += psum[(size_t)i * CC + o];
        q += psq [(size_t)i * CC + o];
    }
    __shared__ float r1[256], r2[256];
    r1[tid] = s; r2[tid] = q; __syncthreads();
    for (int st = 128; st > 0; st >>= 1) {
        if (tid < st) { r1[tid] += r1[tid + st]; r2[tid] += r2[tid + st]; }
        __syncthreads();
    }
    if (tid == 0) {
        const float invM = 1.f / (float)(BB * HW);
        float mean = r1[0] * invM;
        float var  = r2[0] * invM - mean * mean;
        float sc = gamma[o] * rsqrtf(var + 1e-5f);
        g_scale[o] = sc;
        g_shift[o] = beta[o] - mean * sc;
    }
}

// ---------------------------------------------------------------------------
// E-step, M-tile 256, fused 3-term, staggered kk (R11 exact)
// ---------------------------------------------------------------------------
#define EAP 264
#define ESTG_A (32 * EAP * 2)
#define ESTG_B (32 * 72 * 2)
#define EBP 72
#define ESTEP_SMEM (4 * ESTG_A + 4 * ESTG_B)
__global__ __launch_bounds__(256) void estep_mma_kernel(int write_z) {
    extern __shared__ __align__(16) char esm[];
    const int b  = blockIdx.y;
    const int n0 = blockIdx.x * 256;
    const int tid  = threadIdx.x;
    const int lane = tid & 31;
    const int wid  = tid >> 5;
    const int wm   = (wid & 3) * 64;
    const int wn   = (wid >> 2) * 32;
    const int kk0  = (wid & 1) << 4;

    const uint32_t base = smem_u32(esm);
    const uint32_t oAH = 0, oAL = 2 * ESTG_A;
    const uint32_t oBH = 4 * ESTG_A, oBL = 4 * ESTG_A + 2 * ESTG_B;
    float* L = (float*)esm;

    const __nv_bfloat16* Xh = g_xfhi + (size_t)b * CC * HW;
    const __nv_bfloat16* Xl = g_xflo + (size_t)b * CC * HW;
    const __nv_bfloat16* Mh = g_muhi + (size_t)b * CC * KK;
    const __nv_bfloat16* Ml = g_mulo + (size_t)b * CC * KK;

    float acc[4][4][4];
#pragma unroll
    for (int i = 0; i < 4; i++)
#pragma unroll
        for (int j = 0; j < 4; j++)
#pragma unroll
            for (int q = 0; q < 4; q++) acc[i][j][q] = 0.f;

    const int brow = tid >> 3, bcol = (tid & 7) * 8;

    const int NT = 16;
#define LOAD_TILE(IT, BUF) do {                                                   \
        int k0 = (IT) * 32;                                                       \
        uint32_t aH = base + oAH + (BUF) * ESTG_A, aL = base + oAL + (BUF) * ESTG_A; \
        uint32_t bH = base + oBH + (BUF) * ESTG_B, bL = base + oBL + (BUF) * ESTG_B; \
        _Pragma("unroll")                                                          \
        for (int t = 0; t < 4; t++) {                                             \
            int idx = tid + t * 256, r = idx >> 5, c = (idx & 31) * 8;            \
            cp_async16(aH + (r * EAP + c) * 2, Xh + (size_t)(k0 + r) * HW + n0 + c); \
            cp_async16(aL + (r * EAP + c) * 2, Xl + (size_t)(k0 + r) * HW + n0 + c); \
        }                                                                          \
        cp_async16(bH + (brow * EBP + bcol) * 2, Mh + (size_t)(k0 + brow) * KK + bcol); \
        cp_async16(bL + (brow * EBP + bcol) * 2, Ml + (size_t)(k0 + brow) * KK + bcol); \
        asm volatile("cp.async.commit_group;");                                   \
    } while (0)

    LOAD_TILE(0, 0);
    for (int it = 0; it < NT; ++it) {
        if (it + 1 < NT) { LOAD_TILE(it + 1, (it + 1) & 1); asm volatile("cp.async.wait_group 1;"); }
        else             { asm volatile("cp.async.wait_group 0;"); }
        __syncthreads();

        const int buf = it & 1;
        const uint32_t aH = base + oAH + buf * ESTG_A, aL = base + oAL + buf * ESTG_A;
        const uint32_t bH = base + oBH + buf * ESTG_B, bL = base + oBL + buf * ESTG_B;
#pragma unroll
        for (int t = 0; t < 2; t++) {
            const int kk = kk0 ^ (t << 4);
            uint32_t ah[4][4], al[4][4], bh[2][4], bl[2][4];
#pragma unroll
            for (int f = 0; f < 4; f++) {
                uint32_t off = (((kk + (lane & 7) + ((lane >> 4) << 3)) * EAP)
                                + wm + f * 16 + ((lane >> 3) & 1) * 8) * 2;
                ldsm_x4_t(ah[f][0], ah[f][1], ah[f][2], ah[f][3], aH + off);
                ldsm_x4_t(al[f][0], al[f][1], al[f][2], al[f][3], aL + off);
            }
#pragma unroll
            for (int jn = 0; jn < 2; jn++) {
                uint32_t off = (((kk + (lane & 7) + ((lane >> 3) & 1) * 8) * EBP)
                                + wn + jn * 16 + ((lane >> 4) << 3)) * 2;
                ldsm_x4_t(bh[jn][0], bh[jn][1], bh[jn][2], bh[jn][3], bH + off);
                ldsm_x4_t(bl[jn][0], bl[jn][1], bl[jn][2], bl[jn][3], bL + off);
            }
#pragma unroll
            for (int f = 0; f < 4; f++)
#pragma unroll
                for (int jn = 0; jn < 2; jn++) {
                    mma_bf16(acc[f][jn * 2 + 0], ah[f], bh[jn][0], bh[jn][1]);
                    mma_bf16(acc[f][jn * 2 + 1], ah[f], bh[jn][2], bh[jn][3]);
                }
#pragma unroll
            for (int f = 0; f < 4; f++)
#pragma unroll
                for (int jn = 0; jn < 2; jn++) {
                    mma_bf16(acc[f][jn * 2 + 0], al[f], bh[jn][0], bh[jn][1]);
                    mma_bf16(acc[f][jn * 2 + 1], al[f], bh[jn][2], bh[jn][3]);
                }
#pragma unroll
            for (int f = 0; f < 4; f++)
#pragma unroll
                for (int jn = 0; jn < 2; jn++) {
                    mma_bf16(acc[f][jn * 2 + 0], ah[f], bl[jn][0], bl[jn][1]);
                    mma_bf16(acc[f][jn * 2 + 1], ah[f], bl[jn][2], bl[jn][3]);
                }
        }
        __syncthreads();
    }
#undef LOAD_TILE

#pragma unroll
    for (int f = 0; f < 4; f++) {
        int row = wm + f * 16 + (lane >> 2);
#pragma unroll
        for (int j8 = 0; j8 < 4; j8++) {
            int col = wn + j8 * 8 + (lane & 3) * 2;
            *reinterpret_cast<float2*>(&L[row * 68 + col])       = {acc[f][j8][0], acc[f][j8][1]};
            *reinterpret_cast<float2*>(&L[(row + 8) * 68 + col]) = {acc[f][j8][2], acc[f][j8][3]};
        }
    }
    __syncthreads();

    for (int i = 0; i < 32; i++) {
        int r = wid * 32 + i;
        float v0 = L[r * 68 + lane], v1 = L[r * 68 + lane + 32];
        float m = fmaxf(v0, v1);
#pragma unroll
        for (int off = 16; off > 0; off >>= 1)
            m = fmaxf(m, __shfl_xor_sync(0xffffffffu, m, off));
        float e0 = expf(v0 - m), e1 = expf(v1 - m);
        float s = e0 + e1;
#pragma unroll
        for (int off = 16; off > 0; off >>= 1)
            s += __shfl_xor_sync(0xffffffffu, s, off);
        float inv = 1.f / s;
        float z0 = e0 * inv, z1 = e1 * inv;
        size_t zbase = (size_t)b * HW * KK + (size_t)(n0 + r) * KK;
        if (write_z) {
            g_z[zbase + lane]      = z0;
            g_z[zbase + lane + 32] = z1;
        }
        __nv_bfloat16 h, l;
        split_val(z0, h, l); g_zhi[zbase + lane] = h;      g_zlo[zbase + lane] = l;
        split_val(z1, h, l); g_zhi[zbase + lane + 32] = h; g_zlo[zbase + lane + 32] = l;
    }
}

// ---------------------------------------------------------------------------
// M-step, M-tile 256, fused 3-term, staggered kk (R11 exact)
// ---------------------------------------------------------------------------
#define MAP 40
#define MBP 72
#define MSTG_A (256 * MAP * 2)
#define MSTG_B (32 * MBP * 2)
#define MSTEP_SMEM (4 * MSTG_A + 4 * MSTG_B)
__global__ __launch_bounds__(256) void mstep_mma_kernel() {
    extern __shared__ __align__(16) char msm[];
    const int b  = blockIdx.z;
    const int s  = blockIdx.y;
    const int c0 = blockIdx.x * 256;
    const int tid  = threadIdx.x;
    const int lane = tid & 31;
    const int wid  = tid >> 5;
    const int wm   = (wid & 3) * 64;
    const int wn   = (wid >> 2) * 32;
    const int kk0  = (wid & 1) << 4;

    const uint32_t base = smem_u32(msm);
    const uint32_t oAH = 0, oAL = 2 * MSTG_A;
    const uint32_t oBH = 4 * MSTG_A, oBL = 4 * MSTG_A + 2 * MSTG_B;

    const __nv_bfloat16* Xh = g_xfhi + (size_t)b * CC * HW;
    const __nv_bfloat16* Xl = g_xflo + (size_t)b * CC * HW;
    const __nv_bfloat16* Zh = g_zhi  + (size_t)b * HW * KK;
    const __nv_bfloat16* Zl = g_zlo  + (size_t)b * HW * KK;

    float acc[4][4][4];
#pragma unroll
    for (int i = 0; i < 4; i++)
#pragma unroll
        for (int j = 0; j < 4; j++)
#pragma unroll
            for (int q = 0; q < 4; q++) acc[i][j][q] = 0.f;

    const int brow = tid >> 3, bcol = (tid & 7) * 8;

    const int nbeg = s * (HW / SPLIT);
    const int NT = 16;
#define LOAD_TILE(IT, BUF) do {                                                   \
        int n0 = nbeg + (IT) * 32;                                                \
        uint32_t aH = base + oAH + (BUF) * MSTG_A, aL = base + oAL + (BUF) * MSTG_A; \
        uint32_t bH = base + oBH + (BUF) * MSTG_B, bL = base + oBL + (BUF) * MSTG_B; \
        _Pragma("unroll")                                                          \
        for (int t = 0; t < 4; t++) {                                             \
            int idx = tid + t * 256, r = idx >> 2, c = (idx & 3) * 8;             \
            cp_async16(aH + (r * MAP + c) * 2, Xh + (size_t)(c0 + r) * HW + n0 + c); \
            cp_async16(aL + (r * MAP + c) * 2, Xl + (size_t)(c0 + r) * HW + n0 + c); \
        }                                                                          \
        cp_async16(bH + (brow * MBP + bcol) * 2, Zh + (size_t)(n0 + brow) * KK + bcol); \
        cp_async16(bL + (brow * MBP + bcol) * 2, Zl + (size_t)(n0 + brow) * KK + bcol); \
        asm volatile("cp.async.commit_group;");                                   \
    } while (0)

    LOAD_TILE(0, 0);
    for (int it = 0; it < NT; ++it) {
        if (it + 1 < NT) { LOAD_TILE(it + 1, (it + 1) & 1); asm volatile("cp.async.wait_group 1;"); }
        else             { asm volatile("cp.async.wait_group 0;"); }
        __syncthreads();

        const int buf = it & 1;
        const uint32_t aH = base + oAH + buf * MSTG_A, aL = base + oAL + buf * MSTG_A;
        const uint32_t bH = base + oBH + buf * MSTG_B, bL = base + oBL + buf * MSTG_B;
#pragma unroll
        for (int t = 0; t < 2; t++) {
            const int kk = kk0 ^ (t << 4);
            uint32_t ah[4][4], al[4][4], bh[2][4], bl[2][4];
#pragma unroll
            for (int im = 0; im < 4; im++) {
                uint32_t off = (((wm + im * 16 + (lane & 15)) * MAP) + kk + ((lane >> 4) << 3)) * 2;
                ldsm_x4(ah[im][0], ah[im][1], ah[im][2], ah[im][3], aH + off);
                ldsm_x4(al[im][0], al[im][1], al[im][2], al[im][3], aL + off);
            }
#pragma unroll
            for (int jn = 0; jn < 2; jn++) {
                uint32_t off = (((kk + (lane & 7) + ((lane >> 3) & 1) * 8) * MBP)
                                + wn + jn * 16 + ((lane >> 4) << 3)) * 2;
                ldsm_x4_t(bh[jn][0], bh[jn][1], bh[jn][2], bh[jn][3], bH + off);
                ldsm_x4_t(bl[jn][0], bl[jn][1], bl[jn][2], bl[jn][3], bL + off);
            }
#pragma unroll
            for (int im = 0; im < 4; im++)
#pragma unroll
                for (int jn = 0; jn < 2; jn++) {
                    mma_bf16(acc[im][jn * 2 + 0], ah[im], bh[jn][0], bh[jn][1]);
                    mma_bf16(acc[im][jn * 2 + 1], ah[im], bh[jn][2], bh[jn][3]);
                }
#pragma unroll
            for (int im = 0; im < 4; im++)
#pragma unroll
                for (int jn = 0; jn < 2; jn++) {
                    mma_bf16(acc[im][jn * 2 + 0], al[im], bh[jn][0], bh[jn][1]);
                    mma_bf16(acc[im][jn * 2 + 1], al[im], bh[jn][2], bh[jn][3]);
                }
#pragma unroll
            for (int im = 0; im < 4; im++)
#pragma unroll
                for (int jn = 0; jn < 2; jn++) {
                    mma_bf16(acc[im][jn * 2 + 0], ah[im], bl[jn][0], bl[jn][1]);
                    mma_bf16(acc[im][jn * 2 + 1], ah[im], bl[jn][2], bl[jn][3]);
                }
        }
        __syncthreads();
    }
#undef LOAD_TILE

    float* outp = g_mu_part + ((size_t)b * SPLIT + s) * CC * KK;
#pragma unroll
    for (int im = 0; im < 4; im++) {
        int row = c0 + wm + im * 16 + (lane >> 2);
#pragma unroll
        for (int j8 = 0; j8 < 4; j8++) {
            int col = wn + j8 * 8 + (lane & 3) * 2;
            *reinterpret_cast<float2*>(&outp[(size_t)row * KK + col])       = {acc[im][j8][0], acc[im][j8][1]};
            *reinterpret_cast<float2*>(&outp[(size_t)(row + 8) * KK + col]) = {acc[im][j8][2], acc[im][j8][3]};
        }
    }
}

// ---------------------------------------------------------------------------
// Reduce split-K partials + l2-normalize
// ---------------------------------------------------------------------------
__global__ void reduce_l2norm_kernel(float* __restrict__ out_mu) {
    const int bk = blockIdx.x;
    const int b = bk >> 6, k = bk & 63;
    const int tid = threadIdx.x;

    float* mub = g_mu + (size_t)b * CC * KK;
    const float* part = g_mu_part + (size_t)b * SPLIT * CC * KK;

    float s2 = 0.f;
    for (int c = tid; c < CC; c += 128) {
        float v = 0.f;
#pragma unroll
        for (int s = 0; s < SPLIT; s++)
            v += part[(size_t)s * CC * KK + (size_t)c * KK + k];
        mub[(size_t)c * KK + k] = v;
        s2 += v * v;
    }
    __shared__ float red[128];
    red[tid] = s2; __syncthreads();
    for (int st = 64; st > 0; st >>= 1) {
        if (tid < st) red[tid] += red[tid + st];
        __syncthreads();
    }
    float scale = 1.f / (1e-6f + sqrtf(red[0]));
    for (int c = tid; c < CC; c += 128) {
        size_t idx = (size_t)b * CC * KK + (size_t)c * KK + k;
        float v = mub[(size_t)c * KK + k] * scale;
        __nv_bfloat16 h, l; split_val(v, h, l);
        g_muhi[idx] = h; g_mulo[idx] = l;
        if (out_mu) out_mu[idx] = v;
    }
}

// ---------------------------------------------------------------------------
// Reconstruction (unchanged)
// ---------------------------------------------------------------------------
#define RP 40
#define PIPE_WAIT_SYNC(IT, NT)                                   \
    if ((IT) + 2 < (NT)) { asm volatile("cp.async.wait_group 1;"); } \
    else                 { asm volatile("cp.async.wait_group 0;"); } \
    __syncthreads();

__global__ __launch_bounds__(256) void recon_mma_kernel() {
    const int b  = blockIdx.z;
    const int c0 = blockIdx.y * 128;
    const int n0 = blockIdx.x * 128;
    const int tid  = threadIdx.x;
    const int lane = tid & 31;
    const int wid  = tid >> 5;
    const int wm   = (wid & 1) * 64;
    const int wn   = (wid >> 1) * 32;

    __shared__ __nv_bfloat16 As[3][128 * RP];
    __shared__ __nv_bfloat16 Bs[3][128 * RP];

    const __nv_bfloat16* Mh = g_muhi + (size_t)b * CC * KK;
    const __nv_bfloat16* Ml = g_mulo + (size_t)b * CC * KK;
    const __nv_bfloat16* Zh = g_zhi  + (size_t)b * HW * KK;
    const __nv_bfloat16* Zl = g_zlo  + (size_t)b * HW * KK;

    float acc[4][4][4];
#pragma unroll
    for (int i = 0; i < 4; i++)
#pragma unroll
        for (int j = 0; j < 4; j++)
#pragma unroll
            for (int q = 0; q < 4; q++) acc[i][j][q] = 0.f;

    const uint32_t sA0 = smem_u32(As[0]);
    const uint32_t sB0 = smem_u32(Bs[0]);
    const uint32_t ssz = 128 * RP * 2;

    const int aq0 = tid, aq1 = tid + 256;
    const int ar0 = aq0 >> 2, ac0 = (aq0 & 3) * 8;
    const int ar1 = aq1 >> 2, ac1 = (aq1 & 3) * 8;

    const int NT = 6;
#define LOAD_TILE(IT, BUF) do {                                                   \
        int pass = (IT) >> 1, k0 = ((IT) & 1) * 32;                               \
        const __nv_bfloat16* Ap = (pass == 1) ? Ml : Mh;                          \
        const __nv_bfloat16* Bp = (pass == 2) ? Zl : Zh;                          \
        uint32_t sa = sA0 + (BUF) * ssz, sb = sB0 + (BUF) * ssz;                  \
        cp_async16(sa + (ar0 * RP + ac0) * 2, Ap + (size_t)(c0 + ar0) * KK + k0 + ac0); \
        cp_async16(sa + (ar1 * RP + ac1) * 2, Ap + (size_t)(c0 + ar1) * KK + k0 + ac1); \
        cp_async16(sb + (ar0 * RP + ac0) * 2, Bp + (size_t)(n0 + ar0) * KK + k0 + ac0); \
        cp_async16(sb + (ar1 * RP + ac1) * 2, Bp + (size_t)(n0 + ar1) * KK + k0 + ac1); \
        asm volatile("cp.async.commit_group;");                                   \
    } while (0)

    LOAD_TILE(0, 0);
    LOAD_TILE(1, 1);
    int buf = 0;
    for (int it = 0; it < NT; ++it) {
        PIPE_WAIT_SYNC(it, NT);
        if (it + 2 < NT) {
            int nb = buf + 2; if (nb >= 3) nb -= 3;
            LOAD_TILE(it + 2, nb);
        }
        const uint32_t sa = sA0 + buf * ssz;
        const uint32_t sb = sB0 + buf * ssz;
#pragma unroll
        for (int kk = 0; kk < 32; kk += 16) {
            uint32_t a[4][4], bfr[2][4];
#pragma unroll
            for (int im = 0; im < 4; im++) {
                uint32_t addr = sa + (((wm + im * 16 + (lane & 15)) * RP) + kk + ((lane >> 4) << 3)) * 2;
                ldsm_x4(a[im][0], a[im][1], a[im][2], a[im][3], addr);
            }
#pragma unroll
            for (int jn = 0; jn < 2; jn++) {
                uint32_t addr = sb + (((wn + jn * 16 + (lane & 7) + ((lane >> 4) << 3)) * RP)
                                      + kk + ((lane >> 3) & 1) * 8) * 2;
                ldsm_x4(bfr[jn][0], bfr[jn][1], bfr[jn][2], bfr[jn][3], addr);
            }
#pragma unroll
            for (int im = 0; im < 4; im++)
#pragma unroll
                for (int jn = 0; jn < 2; jn++) {
                    mma_bf16(acc[im][jn * 2 + 0], a[im], bfr[jn][0], bfr[jn][1]);
                    mma_bf16(acc[im][jn * 2 + 1], a[im], bfr[jn][2], bfr[jn][3]);
                }
        }
        if (++buf == 3) buf = 0;
    }
#undef LOAD_TILE

    __nv_bfloat16* Oh = g_xrhi + (size_t)b * CC * HW;
    __nv_bfloat16* Ol = g_xrlo + (size_t)b * CC * HW;
#pragma unroll
    for (int im = 0; im < 4; im++) {
        int row = c0 + wm + im * 16 + (lane >> 2);
#pragma unroll
        for (int j8 = 0; j8 < 4; j8++) {
            int col = n0 + wn + j8 * 8 + (lane & 3) * 2;
            __nv_bfloat16 h0, h1, h2, h3, l0, l1, l2, l3;
            split_val(fmaxf(acc[im][j8][0], 0.f), h0, l0);
            split_val(fmaxf(acc[im][j8][1], 0.f), h1, l1);
            split_val(fmaxf(acc[im][j8][2], 0.f), h2, l2);
            split_val(fmaxf(acc[im][j8][3], 0.f), h3, l3);
            *reinterpret_cast<__nv_bfloat162*>(&Oh[(size_t)row * HW + col]) = __nv_bfloat162{h0, h1};
            *reinterpret_cast<__nv_bfloat162*>(&Ol[(size_t)row * HW + col]) = __nv_bfloat162{l0, l1};
            *reinterpret_cast<__nv_bfloat162*>(&Oh[(size_t)(row + 8) * HW + col]) = __nv_bfloat162{h2, h3};
            *reinterpret_cast<__nv_bfloat162*>(&Ol[(size_t)(row + 8) * HW + col]) = __nv_bfloat162{l2, l3};
        }
    }
}

// ---------------------------------------------------------------------------
// final / z-transpose
// ---------------------------------------------------------------------------
__global__ void final_kernel(const float* __restrict__ x, float* __restrict__ out) {
    const int b = blockIdx.z, o = blockIdx.y;
    const size_t base = (size_t)b * CC * HW + (size_t)o * HW
                      + (size_t)blockIdx.x * 1024 + (size_t)threadIdx.x * 4;
    const float sc = g_scale[o], sh = g_shift[o];
    float4 v2 = *reinterpret_cast<const float4*>(&g_buf1[base]);
    float4 vx = *reinterpret_cast<const float4*>(&x[base]);
    float4 r;
    r.x = fmaxf(fmaf(v2.x, sc, sh) + vx.x, 0.f);
    r.y = fmaxf(fmaf(v2.y, sc, sh) + vx.y, 0.f);
    r.z = fmaxf(fmaf(v2.z, sc, sh) + vx.z, 0.f);
    r.w = fmaxf(fmaf(v2.w, sc, sh) + vx.w, 0.f);
    *reinterpret_cast<float4*>(&out[base]) = r;
}

__global__ void zt_kernel(float* __restrict__ zt) {
    const int b  = blockIdx.z;
    const int n0 = blockIdx.x * 32;
    const int k0 = blockIdx.y * 32;
    __shared__ float t[32][33];
    const int tx = threadIdx.x, ty = threadIdx.y;
    const float* zb = g_z + (size_t)b * HW * KK;
#pragma unroll
    for (int c = 0; c < 32; c += 8)
        t[ty + c][tx] = zb[(size_t)(n0 + ty + c) * KK + k0 + tx];
    __syncthreads();
    float* ztb = zt + (size_t)b * KK * HW;
#pragma unroll
    for (int c = 0; c < 32; c += 8)
        ztb[(size_t)(k0 + ty + c) * HW + n0 + tx] = t[tx][ty + c];
}

// ---------------------------------------------------------------------------
// Launch
// ---------------------------------------------------------------------------
extern "C" void kernel_launch(void* const* d_in, const int* in_sizes, int n_in,
                              void* d_out, int out_size) {
    const float* x     = (const float*)d_in[0];
    const float* w1    = (const float*)d_in[1];
    const float* b1    = (const float*)d_in[2];
    const float* w2    = (const float*)d_in[3];
    const float* gamma = (const float*)d_in[4];
    const float* beta  = (const float*)d_in[5];
    const float* mu_in = (const float*)d_in[6];

    float* out    = (float*)d_out;
    float* out_mu = out + (size_t)BB * CC * HW;
    float* out_zt = out_mu + (size_t)BB * CC * KK;

    static int smem_set = 0;
    if (!smem_set) {
        cudaFuncSetAttribute(conv_mma_kernel,  cudaFuncAttributeMaxDynamicSharedMemorySize, CONV_SMEM);
        cudaFuncSetAttribute(estep_mma_kernel, cudaFuncAttributeMaxDynamicSharedMemorySize, ESTEP_SMEM);
        cudaFuncSetAttribute(mstep_mma_kernel, cudaFuncAttributeMaxDynamicSharedMemorySize, MSTEP_SMEM);
        smem_set = 1;
    }

    split_w_kernel<<<CC * CC / 256, 256>>>(w1, w2);
    split_x_kernel<<<(BB * CC * HW) / (256 * 4), 256>>>(x);
    copymu_kernel<<<dim3(CC * KK / 256, BB), 256>>>(mu_in);

    conv_mma_kernel<<<dim3(HW / 256, CC / 128, BB), 512, CONV_SMEM>>>(b1, 0);

    for (int s = 0; s < 3; s++) {
        estep_mma_kernel<<<dim3(HW / 256, BB), 256, ESTEP_SMEM>>>(s == 2 ? 1 : 0);
        mstep_mma_kernel<<<dim3(CC / 256, SPLIT, BB), 256, MSTEP_SMEM>>>();
        reduce_l2norm_kernel<<<BB * KK, 128>>>(s == 2 ? out_mu : nullptr);
    }

    recon_mma_kernel<<<dim3(HW / 128, CC / 128, BB), 256>>>();

    conv_mma_kernel<<<dim3(HW / 256, CC / 128, BB), 512, CONV_SMEM>>>(nullptr, 1);

    bn_final_kernel<<<CC, 256>>>(gamma, beta);
    final_kernel<<<dim3(HW / 1024, CC, BB), 256>>>(x, out);
    zt_kernel<<<dim3(HW / 32, KK / 32, BB), dim3(32, 8)>>>(out_zt);
}

// round 15
// speedup vs baseline: 1.0556x; 1.0556x over previous
#include <cuda_runtime.h>
#include <cuda_bf16.h>
#include <cstdint>
#include <math.h>

#define BB 16
#define CC 512
#define HW 4096
#define KK 64
#define SPLIT 8

// ---------------------------------------------------------------------------
// Scratch
// ---------------------------------------------------------------------------
__device__ float g_buf1[BB * CC * HW];
__device__ float g_mu[BB * CC * KK];
__device__ float g_mu_part[BB * SPLIT * CC * KK]; // mstep partials; BN partials
__device__ float g_scale[CC];
__device__ float g_shift[CC];

__device__ __nv_bfloat16 g_w1hi[CC * CC], g_w1lo[CC * CC];
__device__ __nv_bfloat16 g_w2hi[CC * CC], g_w2lo[CC * CC];
__device__ __nv_bfloat16 g_xhi[BB * CC * HW],  g_xlo[BB * CC * HW];
__device__ __nv_bfloat16 g_xfhi[BB * CC * HW], g_xflo[BB * CC * HW];
__device__ __nv_bfloat16 g_xrhi[BB * CC * HW], g_xrlo[BB * CC * HW];
__device__ __nv_bfloat16 g_zhi[BB * HW * KK],  g_zlo[BB * HW * KK];
__device__ __nv_bfloat16 g_muhi[BB * CC * KK], g_mulo[BB * CC * KK];

#define BN_SLOTS 2048   // 16 b * 32 n-tiles * 4 wn-groups

// ---------------------------------------------------------------------------
// PTX helpers
// ---------------------------------------------------------------------------
__device__ __forceinline__ uint32_t smem_u32(const void* p) {
    return (uint32_t)__cvta_generic_to_shared(p);
}
__device__ __forceinline__ void cp_async16(uint32_t saddr, const void* gaddr) {
    asm volatile("cp.async.cg.shared.global [%0], [%1], 16;" :: "r"(saddr), "l"(gaddr));
}
__device__ __forceinline__ void ldsm_x4(uint32_t& r0, uint32_t& r1, uint32_t& r2, uint32_t& r3, uint32_t a) {
    asm volatile("ldmatrix.sync.aligned.m8n8.x4.shared.b16 {%0,%1,%2,%3}, [%4];"
                 : "=r"(r0), "=r"(r1), "=r"(r2), "=r"(r3) : "r"(a));
}
__device__ __forceinline__ void ldsm_x4_t(uint32_t& r0, uint32_t& r1, uint32_t& r2, uint32_t& r3, uint32_t a) {
    asm volatile("ldmatrix.sync.aligned.m8n8.x4.trans.shared.b16 {%0,%1,%2,%3}, [%4];"
                 : "=r"(r0), "=r"(r1), "=r"(r2), "=r"(r3) : "r"(a));
}
__device__ __forceinline__ void mma_bf16(float* c, const uint32_t* a, uint32_t b0, uint32_t b1) {
    asm volatile("mma.sync.aligned.m16n8k16.row.col.f32.bf16.bf16.f32 "
                 "{%0,%1,%2,%3}, {%4,%5,%6,%7}, {%8,%9}, {%0,%1,%2,%3};"
                 : "+f"(c[0]), "+f"(c[1]), "+f"(c[2]), "+f"(c[3])
                 : "r"(a[0]), "r"(a[1]), "r"(a[2]), "r"(a[3]), "r"(b0), "r"(b1));
}
__device__ __forceinline__ void split_val(float v, __nv_bfloat16& h, __nv_bfloat16& l) {
    h = __float2bfloat16(v);
    l = __float2bfloat16(v - __bfloat162float(h));
}

// ---------------------------------------------------------------------------
// Conversions
// ---------------------------------------------------------------------------
__global__ void split_w_kernel(const float* __restrict__ w1, const float* __restrict__ w2) {
    int i = blockIdx.x * 256 + threadIdx.x;
    split_val(w1[i], g_w1hi[i], g_w1lo[i]);
    split_val(w2[i], g_w2hi[i], g_w2lo[i]);
}
__global__ void split_x_kernel(const float* __restrict__ x) {
    size_t i = ((size_t)blockIdx.x * 256 + threadIdx.x) * 4;
    float4 v = *reinterpret_cast<const float4*>(&x[i]);
    __nv_bfloat16 h0, h1, h2, h3, l0, l1, l2, l3;
    split_val(v.x, h0, l0); split_val(v.y, h1, l1);
    split_val(v.z, h2, l2); split_val(v.w, h3, l3);
    *reinterpret_cast<__nv_bfloat162*>(&g_xhi[i])     = __nv_bfloat162{h0, h1};
    *reinterpret_cast<__nv_bfloat162*>(&g_xhi[i + 2]) = __nv_bfloat162{h2, h3};
    *reinterpret_cast<__nv_bfloat162*>(&g_xlo[i])     = __nv_bfloat162{l0, l1};
    *reinterpret_cast<__nv_bfloat162*>(&g_xlo[i + 2]) = __nv_bfloat162{l2, l3};
}
__global__ void copymu_kernel(const float* __restrict__ mu_in) {
    int b = blockIdx.y;
    int i = blockIdx.x * 256 + threadIdx.x;
    __nv_bfloat16 h, l; split_val(mu_in[i], h, l);
    size_t idx = (size_t)b * CC * KK + i;
    g_muhi[idx] = h; g_mulo[idx] = l;
}

// ---------------------------------------------------------------------------
// conv GEMM (R10 config: 128x128 tiles, 256 thr, 2 CTA/SM; conv2 emits BN partials)
// ---------------------------------------------------------------------------
#define APITCH 40
#define BPITCH 136
#define CSTG_A (128 * APITCH * 2)
#define CSTG_B (32 * BPITCH * 2)
#define CONV_SMEM (4 * CSTG_A + 4 * CSTG_B)

__global__ __launch_bounds__(256) void conv_mma_kernel(const float* __restrict__ bias, int sel) {
    extern __shared__ __align__(16) char csm[];
    const int b  = blockIdx.z;
    const int m0 = blockIdx.y * 128;
    const int n0 = blockIdx.x * 128;
    const int tid  = threadIdx.x;
    const int lane = tid & 31;
    const int wid  = tid >> 5;
    const int wm   = (wid & 1) * 64;
    const int wn   = (wid >> 1) * 32;

    const uint32_t base = smem_u32(csm);
    const uint32_t oAH = 0, oAL = 2 * CSTG_A;
    const uint32_t oBH = 4 * CSTG_A, oBL = 4 * CSTG_A + 2 * CSTG_B;

    const __nv_bfloat16* Whi = sel ? g_w2hi : g_w1hi;
    const __nv_bfloat16* Wlo = sel ? g_w2lo : g_w1lo;
    const __nv_bfloat16* Xhi = (sel ? g_xrhi : g_xhi) + (size_t)b * CC * HW;
    const __nv_bfloat16* Xlo = (sel ? g_xrlo : g_xlo) + (size_t)b * CC * HW;

    float acc[4][4][4];
#pragma unroll
    for (int i = 0; i < 4; i++)
#pragma unroll
        for (int j = 0; j < 4; j++)
#pragma unroll
            for (int q = 0; q < 4; q++) acc[i][j][q] = 0.f;

    const int ar0 = tid >> 2,          ac0 = (tid & 3) * 8;
    const int ar1 = (tid + 256) >> 2,  ac1 = (tid & 3) * 8;
    const int br0 = tid >> 4,          bc0 = (tid & 15) * 8;
    const int br1 = (tid + 256) >> 4,  bc1 = (tid & 15) * 8;

    const int NT = 16;

#define LOAD_TILE(IT, BUF) do {                                                   \
        int k0 = (IT) * 32;                                                       \
        uint32_t aH = base + oAH + (BUF) * CSTG_A, aL = base + oAL + (BUF) * CSTG_A; \
        uint32_t bH = base + oBH + (BUF) * CSTG_B, bL = base + oBL + (BUF) * CSTG_B; \
        cp_async16(aH + (ar0 * APITCH + ac0) * 2, Whi + (size_t)(m0 + ar0) * CC + k0 + ac0); \
        cp_async16(aH + (ar1 * APITCH + ac1) * 2, Whi + (size_t)(m0 + ar1) * CC + k0 + ac1); \
        cp_async16(aL + (ar0 * APITCH + ac0) * 2, Wlo + (size_t)(m0 + ar0) * CC + k0 + ac0); \
        cp_async16(aL + (ar1 * APITCH + ac1) * 2, Wlo + (size_t)(m0 + ar1) * CC + k0 + ac1); \
        cp_async16(bH + (br0 * BPITCH + bc0) * 2, Xhi + (size_t)(k0 + br0) * HW + n0 + bc0); \
        cp_async16(bH + (br1 * BPITCH + bc1) * 2, Xhi + (size_t)(k0 + br1) * HW + n0 + bc1); \
        cp_async16(bL + (br0 * BPITCH + bc0) * 2, Xlo + (size_t)(k0 + br0) * HW + n0 + bc0); \
        cp_async16(bL + (br1 * BPITCH + bc1) * 2, Xlo + (size_t)(k0 + br1) * HW + n0 + bc1); \
        asm volatile("cp.async.commit_group;");                                   \
    } while (0)

    LOAD_TILE(0, 0);
    for (int it = 0; it < NT; ++it) {
        if (it + 1 < NT) { LOAD_TILE(it + 1, (it + 1) & 1); asm volatile("cp.async.wait_group 1;"); }
        else             { asm volatile("cp.async.wait_group 0;"); }
        __syncthreads();

        const int buf = it & 1;
        const uint32_t aH = base + oAH + buf * CSTG_A, aL = base + oAL + buf * CSTG_A;
        const uint32_t bH = base + oBH + buf * CSTG_B, bL = base + oBL + buf * CSTG_B;
#pragma unroll
        for (int kk = 0; kk < 32; kk += 16) {
            uint32_t ah[4][4], al[4][4], bh[2][4], bl[2][4];
#pragma unroll
            for (int im = 0; im < 4; im++) {
                uint32_t off = (((wm + im * 16 + (lane & 15)) * APITCH) + kk + ((lane >> 4) << 3)) * 2;
                ldsm_x4(ah[im][0], ah[im][1], ah[im][2], ah[im][3], aH + off);
                ldsm_x4(al[im][0], al[im][1], al[im][2], al[im][3], aL + off);
            }
#pragma unroll
            for (int jn = 0; jn < 2; jn++) {
                uint32_t off = (((kk + (lane & 7) + ((lane >> 3) & 1) * 8) * BPITCH)
                                + wn + jn * 16 + ((lane >> 4) << 3)) * 2;
                ldsm_x4_t(bh[jn][0], bh[jn][1], bh[jn][2], bh[jn][3], bH + off);
                ldsm_x4_t(bl[jn][0], bl[jn][1], bl[jn][2], bl[jn][3], bL + off);
            }
#pragma unroll
            for (int im = 0; im < 4; im++)
#pragma unroll
                for (int jn = 0; jn < 2; jn++) {
                    mma_bf16(acc[im][jn * 2 + 0], ah[im], bh[jn][0], bh[jn][1]);
                    mma_bf16(acc[im][jn * 2 + 1], ah[im], bh[jn][2], bh[jn][3]);
                }
#pragma unroll
            for (int im = 0; im < 4; im++)
#pragma unroll
                for (int jn = 0; jn < 2; jn++) {
                    mma_bf16(acc[im][jn * 2 + 0], al[im], bh[jn][0], bh[jn][1]);
                    mma_bf16(acc[im][jn * 2 + 1], al[im], bh[jn][2], bh[jn][3]);
                }
#pragma unroll
            for (int im = 0; im < 4; im++)
#pragma unroll
                for (int jn = 0; jn < 2; jn++) {
                    mma_bf16(acc[im][jn * 2 + 0], ah[im], bl[jn][0], bl[jn][1]);
                    mma_bf16(acc[im][jn * 2 + 1], ah[im], bl[jn][2], bl[jn][3]);
                }
        }
        __syncthreads();
    }
#undef LOAD_TILE

    if (sel == 0) {
        __nv_bfloat16* Oh = g_xfhi + (size_t)b * CC * HW;
        __nv_bfloat16* Ol = g_xflo + (size_t)b * CC * HW;
#pragma unroll
        for (int im = 0; im < 4; im++) {
            int row = m0 + wm + im * 16 + (lane >> 2);
            float bv0 = bias[row], bv1 = bias[row + 8];
#pragma unroll
            for (int j8 = 0; j8 < 4; j8++) {
                int col = n0 + wn + j8 * 8 + (lane & 3) * 2;
                __nv_bfloat16 h0, h1, h2, h3, l0, l1, l2, l3;
                split_val(acc[im][j8][0] + bv0, h0, l0);
                split_val(acc[im][j8][1] + bv0, h1, l1);
                split_val(acc[im][j8][2] + bv1, h2, l2);
                split_val(acc[im][j8][3] + bv1, h3, l3);
                *reinterpret_cast<__nv_bfloat162*>(&Oh[(size_t)row * HW + col]) = __nv_bfloat162{h0, h1};
                *reinterpret_cast<__nv_bfloat162*>(&Ol[(size_t)row * HW + col]) = __nv_bfloat162{l0, l1};
                *reinterpret_cast<__nv_bfloat162*>(&Oh[(size_t)(row + 8) * HW + col]) = __nv_bfloat162{h2, h3};
                *reinterpret_cast<__nv_bfloat162*>(&Ol[(size_t)(row + 8) * HW + col]) = __nv_bfloat162{l2, l3};
            }
        }
    } else {
        float* Yb = g_buf1 + (size_t)b * CC * HW;
        float* psum = g_mu_part;
        float* psq  = g_mu_part + (size_t)BN_SLOTS * CC;
        const int slot = ((b * 32 + blockIdx.x) * 4) + (wid >> 1);
#pragma unroll
        for (int im = 0; im < 4; im++) {
            int row = m0 + wm + im * 16 + (lane >> 2);
            float s0 = 0.f, q0 = 0.f, s1 = 0.f, q1 = 0.f;
#pragma unroll
            for (int j8 = 0; j8 < 4; j8++) {
                int col = n0 + wn + j8 * 8 + (lane & 3) * 2;
                float a0 = acc[im][j8][0], a1 = acc[im][j8][1];
                float a2 = acc[im][j8][2], a3 = acc[im][j8][3];
                *reinterpret_cast<float2*>(&Yb[(size_t)row * HW + col]) = {a0, a1};
                *reinterpret_cast<float2*>(&Yb[(size_t)(row + 8) * HW + col]) = {a2, a3};
                s0 += a0 + a1; q0 = fmaf(a0, a0, fmaf(a1, a1, q0));
                s1 += a2 + a3; q1 = fmaf(a2, a2, fmaf(a3, a3, q1));
            }
            s0 += __shfl_xor_sync(0xffffffffu, s0, 1); s0 += __shfl_xor_sync(0xffffffffu, s0, 2);
            q0 += __shfl_xor_sync(0xffffffffu, q0, 1); q0 += __shfl_xor_sync(0xffffffffu, q0, 2);
            s1 += __shfl_xor_sync(0xffffffffu, s1, 1); s1 += __shfl_xor_sync(0xffffffffu, s1, 2);
            q1 += __shfl_xor_sync(0xffffffffu, q1, 1); q1 += __shfl_xor_sync(0xffffffffu, q1, 2);
            if ((lane & 3) == 0) {
                psum[(size_t)slot * CC + row]     = s0;
                psq [(size_t)slot * CC + row]     = q0;
                psum[(size_t)slot * CC + row + 8] = s1;
                psq [(size_t)slot * CC + row + 8] = q1;
            }
        }
    }
}

// ---------------------------------------------------------------------------
// BN finalize
// ---------------------------------------------------------------------------
__global__ void bn_final_kernel(const float* __restrict__ gamma,
                                const float* __restrict__ beta) {
    const int o = blockIdx.x;
    const int tid = threadIdx.x;
    const float* psum = g_mu_part;
    const float* psq  = g_mu_part + (size_t)BN_SLOTS * CC;
    float s = 0.f, q = 0.f;
    for (int i = tid; i < BN_SLOTS; i += 256) {
        s += psum[(size_t)i * CC + o];
        q += psq [(size_t)i * CC + o];
    }
    __shared__ float r1[256], r2[256];
    r1[tid] = s; r2[tid] = q; __syncthreads();
    for (int st = 128; st > 0; st >>= 1) {
        if (tid < st) { r1[tid] += r1[tid + st]; r2[tid] += r2[tid + st]; }
        __syncthreads();
    }
    if (tid == 0) {
        const float invM = 1.f / (float)(BB * HW);
        float mean = r1[0] * invM;
        float var  = r2[0] * invM - mean * mean;
        float sc = gamma[o] * rsqrtf(var + 1e-5f);
        g_scale[o] = sc;
        g_shift[o] = beta[o] - mean * sc;
    }
}

// ---------------------------------------------------------------------------
// E-step, M-tile 256, fused 3-term, staggered kk (R11 exact; no fp32 z write)
// ---------------------------------------------------------------------------
#define EAP 264
#define ESTG_A (32 * EAP * 2)
#define ESTG_B (32 * 72 * 2)
#define EBP 72
#define ESTEP_SMEM (4 * ESTG_A + 4 * ESTG_B)
__global__ __launch_bounds__(256) void estep_mma_kernel() {
    extern __shared__ __align__(16) char esm[];
    const int b  = blockIdx.y;
    const int n0 = blockIdx.x * 256;
    const int tid  = threadIdx.x;
    const int lane = tid & 31;
    const int wid  = tid >> 5;
    const int wm   = (wid & 3) * 64;
    const int wn   = (wid >> 2) * 32;
    const int kk0  = (wid & 1) << 4;

    const uint32_t base = smem_u32(esm);
    const uint32_t oAH = 0, oAL = 2 * ESTG_A;
    const uint32_t oBH = 4 * ESTG_A, oBL = 4 * ESTG_A + 2 * ESTG_B;
    float* L = (float*)esm;

    const __nv_bfloat16* Xh = g_xfhi + (size_t)b * CC * HW;
    const __nv_bfloat16* Xl = g_xflo + (size_t)b * CC * HW;
    const __nv_bfloat16* Mh = g_muhi + (size_t)b * CC * KK;
    const __nv_bfloat16* Ml = g_mulo + (size_t)b * CC * KK;

    float acc[4][4][4];
#pragma unroll
    for (int i = 0; i < 4; i++)
#pragma unroll
        for (int j = 0; j < 4; j++)
#pragma unroll
            for (int q = 0; q < 4; q++) acc[i][j][q] = 0.f;

    const int brow = tid >> 3, bcol = (tid & 7) * 8;

    const int NT = 16;
#define LOAD_TILE(IT, BUF) do {                                                   \
        int k0 = (IT) * 32;                                                       \
        uint32_t aH = base + oAH + (BUF) * ESTG_A, aL = base + oAL + (BUF) * ESTG_A; \
        uint32_t bH = base + oBH + (BUF) * ESTG_B, bL = base + oBL + (BUF) * ESTG_B; \
        _Pragma("unroll")                                                          \
        for (int t = 0; t < 4; t++) {                                             \
            int idx = tid + t * 256, r = idx >> 5, c = (idx & 31) * 8;            \
            cp_async16(aH + (r * EAP + c) * 2, Xh + (size_t)(k0 + r) * HW + n0 + c); \
            cp_async16(aL + (r * EAP + c) * 2, Xl + (size_t)(k0 + r) * HW + n0 + c); \
        }                                                                          \
        cp_async16(bH + (brow * EBP + bcol) * 2, Mh + (size_t)(k0 + brow) * KK + bcol); \
        cp_async16(bL + (brow * EBP + bcol) * 2, Ml + (size_t)(k0 + brow) * KK + bcol); \
        asm volatile("cp.async.commit_group;");                                   \
    } while (0)

    LOAD_TILE(0, 0);
    for (int it = 0; it < NT; ++it) {
        if (it + 1 < NT) { LOAD_TILE(it + 1, (it + 1) & 1); asm volatile("cp.async.wait_group 1;"); }
        else             { asm volatile("cp.async.wait_group 0;"); }
        __syncthreads();

        const int buf = it & 1;
        const uint32_t aH = base + oAH + buf * ESTG_A, aL = base + oAL + buf * ESTG_A;
        const uint32_t bH = base + oBH + buf * ESTG_B, bL = base + oBL + buf * ESTG_B;
#pragma unroll
        for (int t = 0; t < 2; t++) {
            const int kk = kk0 ^ (t << 4);
            uint32_t ah[4][4], al[4][4], bh[2][4], bl[2][4];
#pragma unroll
            for (int f = 0; f < 4; f++) {
                uint32_t off = (((kk + (lane & 7) + ((lane >> 4) << 3)) * EAP)
                                + wm + f * 16 + ((lane >> 3) & 1) * 8) * 2;
                ldsm_x4_t(ah[f][0], ah[f][1], ah[f][2], ah[f][3], aH + off);
                ldsm_x4_t(al[f][0], al[f][1], al[f][2], al[f][3], aL + off);
            }
#pragma unroll
            for (int jn = 0; jn < 2; jn++) {
                uint32_t off = (((kk + (lane & 7) + ((lane >> 3) & 1) * 8) * EBP)
                                + wn + jn * 16 + ((lane >> 4) << 3)) * 2;
                ldsm_x4_t(bh[jn][0], bh[jn][1], bh[jn][2], bh[jn][3], bH + off);
                ldsm_x4_t(bl[jn][0], bl[jn][1], bl[jn][2], bl[jn][3], bL + off);
            }
#pragma unroll
            for (int f = 0; f < 4; f++)
#pragma unroll
                for (int jn = 0; jn < 2; jn++) {
                    mma_bf16(acc[f][jn * 2 + 0], ah[f], bh[jn][0], bh[jn][1]);
                    mma_bf16(acc[f][jn * 2 + 1], ah[f], bh[jn][2], bh[jn][3]);
                }
#pragma unroll
            for (int f = 0; f < 4; f++)
#pragma unroll
                for (int jn = 0; jn < 2; jn++) {
                    mma_bf16(acc[f][jn * 2 + 0], al[f], bh[jn][0], bh[jn][1]);
                    mma_bf16(acc[f][jn * 2 + 1], al[f], bh[jn][2], bh[jn][3]);
                }
#pragma unroll
            for (int f = 0; f < 4; f++)
#pragma unroll
                for (int jn = 0; jn < 2; jn++) {
                    mma_bf16(acc[f][jn * 2 + 0], ah[f], bl[jn][0], bl[jn][1]);
                    mma_bf16(acc[f][jn * 2 + 1], ah[f], bl[jn][2], bl[jn][3]);
                }
        }
        __syncthreads();
    }
#undef LOAD_TILE

#pragma unroll
    for (int f = 0; f < 4; f++) {
        int row = wm + f * 16 + (lane >> 2);
#pragma unroll
        for (int j8 = 0; j8 < 4; j8++) {
            int col = wn + j8 * 8 + (lane & 3) * 2;
            *reinterpret_cast<float2*>(&L[row * 68 + col])       = {acc[f][j8][0], acc[f][j8][1]};
            *reinterpret_cast<float2*>(&L[(row + 8) * 68 + col]) = {acc[f][j8][2], acc[f][j8][3]};
        }
    }
    __syncthreads();

    for (int i = 0; i < 32; i++) {
        int r = wid * 32 + i;
        float v0 = L[r * 68 + lane], v1 = L[r * 68 + lane + 32];
        float m = fmaxf(v0, v1);
#pragma unroll
        for (int off = 16; off > 0; off >>= 1)
            m = fmaxf(m, __shfl_xor_sync(0xffffffffu, m, off));
        float e0 = expf(v0 - m), e1 = expf(v1 - m);
        float s = e0 + e1;
#pragma unroll
        for (int off = 16; off > 0; off >>= 1)
            s += __shfl_xor_sync(0xffffffffu, s, off);
        float inv = 1.f / s;
        float z0 = e0 * inv, z1 = e1 * inv;
        size_t zbase = (size_t)b * HW * KK + (size_t)(n0 + r) * KK;
        __nv_bfloat16 h, l;
        split_val(z0, h, l); g_zhi[zbase + lane] = h;      g_zlo[zbase + lane] = l;
        split_val(z1, h, l); g_zhi[zbase + lane + 32] = h; g_zlo[zbase + lane + 32] = l;
    }
}

// ---------------------------------------------------------------------------
// M-step, M-tile 256, fused 3-term, staggered kk (R11 exact)
// ---------------------------------------------------------------------------
#define MAP 40
#define MBP 72
#define MSTG_A (256 * MAP * 2)
#define MSTG_B (32 * MBP * 2)
#define MSTEP_SMEM (4 * MSTG_A + 4 * MSTG_B)
__global__ __launch_bounds__(256) void mstep_mma_kernel() {
    extern __shared__ __align__(16) char msm[];
    const int b  = blockIdx.z;
    const int s  = blockIdx.y;
    const int c0 = blockIdx.x * 256;
    const int tid  = threadIdx.x;
    const int lane = tid & 31;
    const int wid  = tid >> 5;
    const int wm   = (wid & 3) * 64;
    const int wn   = (wid >> 2) * 32;
    const int kk0  = (wid & 1) << 4;

    const uint32_t base = smem_u32(msm);
    const uint32_t oAH = 0, oAL = 2 * MSTG_A;
    const uint32_t oBH = 4 * MSTG_A, oBL = 4 * MSTG_A + 2 * MSTG_B;

    const __nv_bfloat16* Xh = g_xfhi + (size_t)b * CC * HW;
    const __nv_bfloat16* Xl = g_xflo + (size_t)b * CC * HW;
    const __nv_bfloat16* Zh = g_zhi  + (size_t)b * HW * KK;
    const __nv_bfloat16* Zl = g_zlo  + (size_t)b * HW * KK;

    float acc[4][4][4];
#pragma unroll
    for (int i = 0; i < 4; i++)
#pragma unroll
        for (int j = 0; j < 4; j++)
#pragma unroll
            for (int q = 0; q < 4; q++) acc[i][j][q] = 0.f;

    const int brow = tid >> 3, bcol = (tid & 7) * 8;

    const int nbeg = s * (HW / SPLIT);
    const int NT = 16;
#define LOAD_TILE(IT, BUF) do {                                                   \
        int n0 = nbeg + (IT) * 32;                                                \
        uint32_t aH = base + oAH + (BUF) * MSTG_A, aL = base + oAL + (BUF) * MSTG_A; \
        uint32_t bH = base + oBH + (BUF) * MSTG_B, bL = base + oBL + (BUF) * MSTG_B; \
        _Pragma("unroll")                                                          \
        for (int t = 0; t < 4; t++) {                                             \
            int idx = tid + t * 256, r = idx >> 2, c = (idx & 3) * 8;             \
            cp_async16(aH + (r * MAP + c) * 2, Xh + (size_t)(c0 + r) * HW + n0 + c); \
            cp_async16(aL + (r * MAP + c) * 2, Xl + (size_t)(c0 + r) * HW + n0 + c); \
        }                                                                          \
        cp_async16(bH + (brow * MBP + bcol) * 2, Zh + (size_t)(n0 + brow) * KK + bcol); \
        cp_async16(bL + (brow * MBP + bcol) * 2, Zl + (size_t)(n0 + brow) * KK + bcol); \
        asm volatile("cp.async.commit_group;");                                   \
    } while (0)

    LOAD_TILE(0, 0);
    for (int it = 0; it < NT; ++it) {
        if (it + 1 < NT) { LOAD_TILE(it + 1, (it + 1) & 1); asm volatile("cp.async.wait_group 1;"); }
        else             { asm volatile("cp.async.wait_group 0;"); }
        __syncthreads();

        const int buf = it & 1;
        const uint32_t aH = base + oAH + buf * MSTG_A, aL = base + oAL + buf * MSTG_A;
        const uint32_t bH = base + oBH + buf * MSTG_B, bL = base + oBL + buf * MSTG_B;
#pragma unroll
        for (int t = 0; t < 2; t++) {
            const int kk = kk0 ^ (t << 4);
            uint32_t ah[4][4], al[4][4], bh[2][4], bl[2][4];
#pragma unroll
            for (int im = 0; im < 4; im++) {
                uint32_t off = (((wm + im * 16 + (lane & 15)) * MAP) + kk + ((lane >> 4) << 3)) * 2;
                ldsm_x4(ah[im][0], ah[im][1], ah[im][2], ah[im][3], aH + off);
                ldsm_x4(al[im][0], al[im][1], al[im][2], al[im][3], aL + off);
            }
#pragma unroll
            for (int jn = 0; jn < 2; jn++) {
                uint32_t off = (((kk + (lane & 7) + ((lane >> 3) & 1) * 8) * MBP)
                                + wn + jn * 16 + ((lane >> 4) << 3)) * 2;
                ldsm_x4_t(bh[jn][0], bh[jn][1], bh[jn][2], bh[jn][3], bH + off);
                ldsm_x4_t(bl[jn][0], bl[jn][1], bl[jn][2], bl[jn][3], bL + off);
            }
#pragma unroll
            for (int im = 0; im < 4; im++)
#pragma unroll
                for (int jn = 0; jn < 2; jn++) {
                    mma_bf16(acc[im][jn * 2 + 0], ah[im], bh[jn][0], bh[jn][1]);
                    mma_bf16(acc[im][jn * 2 + 1], ah[im], bh[jn][2], bh[jn][3]);
                }
#pragma unroll
            for (int im = 0; im < 4; im++)
#pragma unroll
                for (int jn = 0; jn < 2; jn++) {
                    mma_bf16(acc[im][jn * 2 + 0], al[im], bh[jn][0], bh[jn][1]);
                    mma_bf16(acc[im][jn * 2 + 1], al[im], bh[jn][2], bh[jn][3]);
                }
#pragma unroll
            for (int im = 0; im < 4; im++)
#pragma unroll
                for (int jn = 0; jn < 2; jn++) {
                    mma_bf16(acc[im][jn * 2 + 0], ah[im], bl[jn][0], bl[jn][1]);
                    mma_bf16(acc[im][jn * 2 + 1], ah[im], bl[jn][2], bl[jn][3]);
                }
        }
        __syncthreads();
    }
#undef LOAD_TILE

    float* outp = g_mu_part + ((size_t)b * SPLIT + s) * CC * KK;
#pragma unroll
    for (int im = 0; im < 4; im++) {
        int row = c0 + wm + im * 16 + (lane >> 2);
#pragma unroll
        for (int j8 = 0; j8 < 4; j8++) {
            int col = wn + j8 * 8 + (lane & 3) * 2;
            *reinterpret_cast<float2*>(&outp[(size_t)row * KK + col])       = {acc[im][j8][0], acc[im][j8][1]};
            *reinterpret_cast<float2*>(&outp[(size_t)(row + 8) * KK + col]) = {acc[im][j8][2], acc[im][j8][3]};
        }
    }
}

// ---------------------------------------------------------------------------
// Reduce split-K partials + l2-normalize
// ---------------------------------------------------------------------------
__global__ void reduce_l2norm_kernel(float* __restrict__ out_mu) {
    const int bk = blockIdx.x;
    const int b = bk >> 6, k = bk & 63;
    const int tid = threadIdx.x;

    float* mub = g_mu + (size_t)b * CC * KK;
    const float* part = g_mu_part + (size_t)b * SPLIT * CC * KK;

    float s2 = 0.f;
    for (int c = tid; c < CC; c += 128) {
        float v = 0.f;
#pragma unroll
        for (int s = 0; s < SPLIT; s++)
            v += part[(size_t)s * CC * KK + (size_t)c * KK + k];
        mub[(size_t)c * KK + k] = v;
        s2 += v * v;
    }
    __shared__ float red[128];
    red[tid] = s2; __syncthreads();
    for (int st = 64; st > 0; st >>= 1) {
        if (tid < st) red[tid] += red[tid + st];
        __syncthreads();
    }
    float scale = 1.f / (1e-6f + sqrtf(red[0]));
    for (int c = tid; c < CC; c += 128) {
        size_t idx = (size_t)b * CC * KK + (size_t)c * KK + k;
        float v = mub[(size_t)c * KK + k] * scale;
        __nv_bfloat16 h, l; split_val(v, h, l);
        g_muhi[idx] = h; g_mulo[idx] = l;
        if (out_mu) out_mu[idx] = v;
    }
}

// ---------------------------------------------------------------------------
// Reconstruction (unchanged)
// ---------------------------------------------------------------------------
#define RP 40
#define PIPE_WAIT_SYNC(IT, NT)                                   \
    if ((IT) + 2 < (NT)) { asm volatile("cp.async.wait_group 1;"); } \
    else                 { asm volatile("cp.async.wait_group 0;"); } \
    __syncthreads();

__global__ __launch_bounds__(256) void recon_mma_kernel() {
    const int b  = blockIdx.z;
    const int c0 = blockIdx.y * 128;
    const int n0 = blockIdx.x * 128;
    const int tid  = threadIdx.x;
    const int lane = tid & 31;
    const int wid  = tid >> 5;
    const int wm   = (wid & 1) * 64;
    const int wn   = (wid >> 1) * 32;

    __shared__ __nv_bfloat16 As[3][128 * RP];
    __shared__ __nv_bfloat16 Bs[3][128 * RP];

    const __nv_bfloat16* Mh = g_muhi + (size_t)b * CC * KK;
    const __nv_bfloat16* Ml = g_mulo + (size_t)b * CC * KK;
    const __nv_bfloat16* Zh = g_zhi  + (size_t)b * HW * KK;
    const __nv_bfloat16* Zl = g_zlo  + (size_t)b * HW * KK;

    float acc[4][4][4];
#pragma unroll
    for (int i = 0; i < 4; i++)
#pragma unroll
        for (int j = 0; j < 4; j++)
#pragma unroll
            for (int q = 0; q < 4; q++) acc[i][j][q] = 0.f;

    const uint32_t sA0 = smem_u32(As[0]);
    const uint32_t sB0 = smem_u32(Bs[0]);
    const uint32_t ssz = 128 * RP * 2;

    const int aq0 = tid, aq1 = tid + 256;
    const int ar0 = aq0 >> 2, ac0 = (aq0 & 3) * 8;
    const int ar1 = aq1 >> 2, ac1 = (aq1 & 3) * 8;

    const int NT = 6;
#define LOAD_TILE(IT, BUF) do {                                                   \
        int pass = (IT) >> 1, k0 = ((IT) & 1) * 32;                               \
        const __nv_bfloat16* Ap = (pass == 1) ? Ml : Mh;                          \
        const __nv_bfloat16* Bp = (pass == 2) ? Zl : Zh;                          \
        uint32_t sa = sA0 + (BUF) * ssz, sb = sB0 + (BUF) * ssz;                  \
        cp_async16(sa + (ar0 * RP + ac0) * 2, Ap + (size_t)(c0 + ar0) * KK + k0 + ac0); \
        cp_async16(sa + (ar1 * RP + ac1) * 2, Ap + (size_t)(c0 + ar1) * KK + k0 + ac1); \
        cp_async16(sb + (ar0 * RP + ac0) * 2, Bp + (size_t)(n0 + ar0) * KK + k0 + ac0); \
        cp_async16(sb + (ar1 * RP + ac1) * 2, Bp + (size_t)(n0 + ar1) * KK + k0 + ac1); \
        asm volatile("cp.async.commit_group;");                                   \
    } while (0)

    LOAD_TILE(0, 0);
    LOAD_TILE(1, 1);
    int buf = 0;
    for (int it = 0; it < NT; ++it) {
        PIPE_WAIT_SYNC(it, NT);
        if (it + 2 < NT) {
            int nb = buf + 2; if (nb >= 3) nb -= 3;
            LOAD_TILE(it + 2, nb);
        }
        const uint32_t sa = sA0 + buf * ssz;
        const uint32_t sb = sB0 + buf * ssz;
#pragma unroll
        for (int kk = 0; kk < 32; kk += 16) {
            uint32_t a[4][4], bfr[2][4];
#pragma unroll
            for (int im = 0; im < 4; im++) {
                uint32_t addr = sa + (((wm + im * 16 + (lane & 15)) * RP) + kk + ((lane >> 4) << 3)) * 2;
                ldsm_x4(a[im][0], a[im][1], a[im][2], a[im][3], addr);
            }
#pragma unroll
            for (int jn = 0; jn < 2; jn++) {
                uint32_t addr = sb + (((wn + jn * 16 + (lane & 7) + ((lane >> 4) << 3)) * RP)
                                      + kk + ((lane >> 3) & 1) * 8) * 2;
                ldsm_x4(bfr[jn][0], bfr[jn][1], bfr[jn][2], bfr[jn][3], addr);
            }
#pragma unroll
            for (int im = 0; im < 4; im++)
#pragma unroll
                for (int jn = 0; jn < 2; jn++) {
                    mma_bf16(acc[im][jn * 2 + 0], a[im], bfr[jn][0], bfr[jn][1]);
                    mma_bf16(acc[im][jn * 2 + 1], a[im], bfr[jn][2], bfr[jn][3]);
                }
        }
        if (++buf == 3) buf = 0;
    }
#undef LOAD_TILE

    __nv_bfloat16* Oh = g_xrhi + (size_t)b * CC * HW;
    __nv_bfloat16* Ol = g_xrlo + (size_t)b * CC * HW;
#pragma unroll
    for (int im = 0; im < 4; im++) {
        int row = c0 + wm + im * 16 + (lane >> 2);
#pragma unroll
        for (int j8 = 0; j8 < 4; j8++) {
            int col = n0 + wn + j8 * 8 + (lane & 3) * 2;
            __nv_bfloat16 h0, h1, h2, h3, l0, l1, l2, l3;
            split_val(fmaxf(acc[im][j8][0], 0.f), h0, l0);
            split_val(fmaxf(acc[im][j8][1], 0.f), h1, l1);
            split_val(fmaxf(acc[im][j8][2], 0.f), h2, l2);
            split_val(fmaxf(acc[im][j8][3], 0.f), h3, l3);
            *reinterpret_cast<__nv_bfloat162*>(&Oh[(size_t)row * HW + col]) = __nv_bfloat162{h0, h1};
            *reinterpret_cast<__nv_bfloat162*>(&Ol[(size_t)row * HW + col]) = __nv_bfloat162{l0, l1};
            *reinterpret_cast<__nv_bfloat162*>(&Oh[(size_t)(row + 8) * HW + col]) = __nv_bfloat162{h2, h3};
            *reinterpret_cast<__nv_bfloat162*>(&Ol[(size_t)(row + 8) * HW + col]) = __nv_bfloat162{l2, l3};
        }
    }
}

// ---------------------------------------------------------------------------
// final / z-transpose (zt reconstructs z = hi + lo from splits)
// ---------------------------------------------------------------------------
__global__ void final_kernel(const float* __restrict__ x, float* __restrict__ out) {
    const int b = blockIdx.z, o = blockIdx.y;
    const size_t base = (size_t)b * CC * HW + (size_t)o * HW
                      + (size_t)blockIdx.x * 1024 + (size_t)threadIdx.x * 4;
    const float sc = g_scale[o], sh = g_shift[o];
    float4 v2 = *reinterpret_cast<const float4*>(&g_buf1[base]);
    float4 vx = *reinterpret_cast<const float4*>(&x[base]);
    float4 r;
    r.x = fmaxf(fmaf(v2.x, sc, sh) + vx.x, 0.f);
    r.y = fmaxf(fmaf(v2.y, sc, sh) + vx.y, 0.f);
    r.z = fmaxf(fmaf(v2.z, sc, sh) + vx.z, 0.f);
    r.w = fmaxf(fmaf(v2.w, sc, sh) + vx.w, 0.f);
    *reinterpret_cast<float4*>(&out[base]) = r;
}

__global__ void zt_kernel(float* __restrict__ zt) {
    const int b  = blockIdx.z;
    const int n0 = blockIdx.x * 32;
    const int k0 = blockIdx.y * 32;
    __shared__ float t[32][33];
    const int tx = threadIdx.x, ty = threadIdx.y;
    const __nv_bfloat16* zh = g_zhi + (size_t)b * HW * KK;
    const __nv_bfloat16* zl = g_zlo + (size_t)b * HW * KK;
#pragma unroll
    for (int c = 0; c < 32; c += 8) {
        size_t idx = (size_t)(n0 + ty + c) * KK + k0 + tx;
        t[ty + c][tx] = __bfloat162float(zh[idx]) + __bfloat162float(zl[idx]);
    }
    __syncthreads();
    float* ztb = zt + (size_t)b * KK * HW;
#pragma unroll
    for (int c = 0; c < 32; c += 8)
        ztb[(size_t)(k0 + ty + c) * HW + n0 + tx] = t[tx][ty + c];
}

// ---------------------------------------------------------------------------
// Launch
// ---------------------------------------------------------------------------
extern "C" void kernel_launch(void* const* d_in, const int* in_sizes, int n_in,
                              void* d_out, int out_size) {
    const float* x     = (const float*)d_in[0];
    const float* w1    = (const float*)d_in[1];
    const float* b1    = (const float*)d_in[2];
    const float* w2    = (const float*)d_in[3];
    const float* gamma = (const float*)d_in[4];
    const float* beta  = (const float*)d_in[5];
    const float* mu_in = (const float*)d_in[6];

    float* out    = (float*)d_out;
    float* out_mu = out + (size_t)BB * CC * HW;
    float* out_zt = out_mu + (size_t)BB * CC * KK;

    static int smem_set = 0;
    if (!smem_set) {
        cudaFuncSetAttribute(conv_mma_kernel,  cudaFuncAttributeMaxDynamicSharedMemorySize, CONV_SMEM);
        cudaFuncSetAttribute(estep_mma_kernel, cudaFuncAttributeMaxDynamicSharedMemorySize, ESTEP_SMEM);
        cudaFuncSetAttribute(mstep_mma_kernel, cudaFuncAttributeMaxDynamicSharedMemorySize, MSTEP_SMEM);
        smem_set = 1;
    }

    split_w_kernel<<<CC * CC / 256, 256>>>(w1, w2);
    split_x_kernel<<<(BB * CC * HW) / (256 * 4), 256>>>(x);
    copymu_kernel<<<dim3(CC * KK / 256, BB), 256>>>(mu_in);

    conv_mma_kernel<<<dim3(HW / 128, CC / 128, BB), 256, CONV_SMEM>>>(b1, 0);

    for (int s = 0; s < 3; s++) {
        estep_mma_kernel<<<dim3(HW / 256, BB), 256, ESTEP_SMEM>>>();
        mstep_mma_kernel<<<dim3(CC / 256, SPLIT, BB), 256, MSTEP_SMEM>>>();
        reduce_l2norm_kernel<<<BB * KK, 128>>>(s == 2 ? out_mu : nullptr);
    }

    recon_mma_kernel<<<dim3(HW / 128, CC / 128, BB), 256>>>();

    conv_mma_kernel<<<dim3(HW / 128, CC / 128, BB), 256, CONV_SMEM>>>(nullptr, 1);

    bn_final_kernel<<<CC, 256>>>(gamma, beta);
    final_kernel<<<dim3(HW / 1024, CC, BB), 256>>>(x, out);
    zt_kernel<<<dim3(HW / 32, KK / 32, BB), dim3(32, 8)>>>(out_zt);
}

// round 16
// speedup vs baseline: 1.0739x; 1.0174x over previous
#include <cuda_runtime.h>
#include <cuda_bf16.h>
#include <cstdint>
#include <math.h>

#define BB 16
#define CC 512
#define HW 4096
#define KK 64
#define SPLIT 8

// ---------------------------------------------------------------------------
// Scratch
// ---------------------------------------------------------------------------
__device__ float g_buf1[BB * CC * HW];
__device__ float g_mu_part[BB * SPLIT * CC * KK]; // mstep partials; BN partials
__device__ float g_scale[CC];
__device__ float g_shift[CC];

__device__ __nv_bfloat16 g_w1hi[CC * CC], g_w1lo[CC * CC];
__device__ __nv_bfloat16 g_w2hi[CC * CC], g_w2lo[CC * CC];
__device__ __nv_bfloat16 g_xhi[BB * CC * HW],  g_xlo[BB * CC * HW];
__device__ __nv_bfloat16 g_xfhi[BB * CC * HW], g_xflo[BB * CC * HW];
__device__ __nv_bfloat16 g_xrhi[BB * CC * HW], g_xrlo[BB * CC * HW];
__device__ __nv_bfloat16 g_zhi[BB * HW * KK],  g_zlo[BB * HW * KK];
__device__ __nv_bfloat16 g_muhi[BB * CC * KK], g_mulo[BB * CC * KK];

#define BN_SLOTS 2048   // 16 b * 32 n-tiles * 4 wn-groups

// ---------------------------------------------------------------------------
// PTX helpers
// ---------------------------------------------------------------------------
__device__ __forceinline__ uint32_t smem_u32(const void* p) {
    return (uint32_t)__cvta_generic_to_shared(p);
}
__device__ __forceinline__ void cp_async16(uint32_t saddr, const void* gaddr) {
    asm volatile("cp.async.cg.shared.global [%0], [%1], 16;" :: "r"(saddr), "l"(gaddr));
}
__device__ __forceinline__ void ldsm_x4(uint32_t& r0, uint32_t& r1, uint32_t& r2, uint32_t& r3, uint32_t a) {
    asm volatile("ldmatrix.sync.aligned.m8n8.x4.shared.b16 {%0,%1,%2,%3}, [%4];"
                 : "=r"(r0), "=r"(r1), "=r"(r2), "=r"(r3) : "r"(a));
}
__device__ __forceinline__ void ldsm_x4_t(uint32_t& r0, uint32_t& r1, uint32_t& r2, uint32_t& r3, uint32_t a) {
    asm volatile("ldmatrix.sync.aligned.m8n8.x4.trans.shared.b16 {%0,%1,%2,%3}, [%4];"
                 : "=r"(r0), "=r"(r1), "=r"(r2), "=r"(r3) : "r"(a));
}
__device__ __forceinline__ void mma_bf16(float* c, const uint32_t* a, uint32_t b0, uint32_t b1) {
    asm volatile("mma.sync.aligned.m16n8k16.row.col.f32.bf16.bf16.f32 "
                 "{%0,%1,%2,%3}, {%4,%5,%6,%7}, {%8,%9}, {%0,%1,%2,%3};"
                 : "+f"(c[0]), "+f"(c[1]), "+f"(c[2]), "+f"(c[3])
                 : "r"(a[0]), "r"(a[1]), "r"(a[2]), "r"(a[3]), "r"(b0), "r"(b1));
}
__device__ __forceinline__ void split_val(float v, __nv_bfloat16& h, __nv_bfloat16& l) {
    h = __float2bfloat16(v);
    l = __float2bfloat16(v - __bfloat162float(h));
}

// ---------------------------------------------------------------------------
// Fused prologue conversions: one launch.
// Blocks [0, NXB)           : split x (float4 per thread)
// Blocks [NXB, NXB+NWB)     : split w1/w2
// Blocks [NXB+NWB, +NMB*BB) : replicate+split mu
// ---------------------------------------------------------------------------
#define NXB ((BB * CC * HW) / (256 * 4))   // 32768
#define NWB (CC * CC / 256)                // 1024
#define NMB (CC * KK / 256)                // 128

__global__ void prologue_kernel(const float* __restrict__ x,
                                const float* __restrict__ w1,
                                const float* __restrict__ w2,
                                const float* __restrict__ mu_in) {
    int blk = blockIdx.x;
    if (blk < NXB) {
        size_t i = ((size_t)blk * 256 + threadIdx.x) * 4;
        float4 v = *reinterpret_cast<const float4*>(&x[i]);
        __nv_bfloat16 h0, h1, h2, h3, l0, l1, l2, l3;
        split_val(v.x, h0, l0); split_val(v.y, h1, l1);
        split_val(v.z, h2, l2); split_val(v.w, h3, l3);
        *reinterpret_cast<__nv_bfloat162*>(&g_xhi[i])     = __nv_bfloat162{h0, h1};
        *reinterpret_cast<__nv_bfloat162*>(&g_xhi[i + 2]) = __nv_bfloat162{h2, h3};
        *reinterpret_cast<__nv_bfloat162*>(&g_xlo[i])     = __nv_bfloat162{l0, l1};
        *reinterpret_cast<__nv_bfloat162*>(&g_xlo[i + 2]) = __nv_bfloat162{l2, l3};
    } else if (blk < NXB + NWB) {
        int i = (blk - NXB) * 256 + threadIdx.x;
        split_val(w1[i], g_w1hi[i], g_w1lo[i]);
        split_val(w2[i], g_w2hi[i], g_w2lo[i]);
    } else {
        int r = blk - NXB - NWB;           // 0 .. NMB*BB-1
        int b = r / NMB;
        int i = (r % NMB) * 256 + threadIdx.x;
        __nv_bfloat16 h, l; split_val(mu_in[i], h, l);
        size_t idx = (size_t)b * CC * KK + i;
        g_muhi[idx] = h; g_mulo[idx] = l;
    }
}

// ---------------------------------------------------------------------------
// conv GEMM (R10 config: 128x128 tiles, 256 thr, 2 CTA/SM; conv2 emits BN partials)
// ---------------------------------------------------------------------------
#define APITCH 40
#define BPITCH 136
#define CSTG_A (128 * APITCH * 2)
#define CSTG_B (32 * BPITCH * 2)
#define CONV_SMEM (4 * CSTG_A + 4 * CSTG_B)

__global__ __launch_bounds__(256) void conv_mma_kernel(const float* __restrict__ bias, int sel) {
    extern __shared__ __align__(16) char csm[];
    const int b  = blockIdx.z;
    const int m0 = blockIdx.y * 128;
    const int n0 = blockIdx.x * 128;
    const int tid  = threadIdx.x;
    const int lane = tid & 31;
    const int wid  = tid >> 5;
    const int wm   = (wid & 1) * 64;
    const int wn   = (wid >> 1) * 32;

    const uint32_t base = smem_u32(csm);
    const uint32_t oAH = 0, oAL = 2 * CSTG_A;
    const uint32_t oBH = 4 * CSTG_A, oBL = 4 * CSTG_A + 2 * CSTG_B;

    const __nv_bfloat16* Whi = sel ? g_w2hi : g_w1hi;
    const __nv_bfloat16* Wlo = sel ? g_w2lo : g_w1lo;
    const __nv_bfloat16* Xhi = (sel ? g_xrhi : g_xhi) + (size_t)b * CC * HW;
    const __nv_bfloat16* Xlo = (sel ? g_xrlo : g_xlo) + (size_t)b * CC * HW;

    float acc[4][4][4];
#pragma unroll
    for (int i = 0; i < 4; i++)
#pragma unroll
        for (int j = 0; j < 4; j++)
#pragma unroll
            for (int q = 0; q < 4; q++) acc[i][j][q] = 0.f;

    const int ar0 = tid >> 2,          ac0 = (tid & 3) * 8;
    const int ar1 = (tid + 256) >> 2,  ac1 = (tid & 3) * 8;
    const int br0 = tid >> 4,          bc0 = (tid & 15) * 8;
    const int br1 = (tid + 256) >> 4,  bc1 = (tid & 15) * 8;

    const int NT = 16;

#define LOAD_TILE(IT, BUF) do {                                                   \
        int k0 = (IT) * 32;                                                       \
        uint32_t aH = base + oAH + (BUF) * CSTG_A, aL = base + oAL + (BUF) * CSTG_A; \
        uint32_t bH = base + oBH + (BUF) * CSTG_B, bL = base + oBL + (BUF) * CSTG_B; \
        cp_async16(aH + (ar0 * APITCH + ac0) * 2, Whi + (size_t)(m0 + ar0) * CC + k0 + ac0); \
        cp_async16(aH + (ar1 * APITCH + ac1) * 2, Whi + (size_t)(m0 + ar1) * CC + k0 + ac1); \
        cp_async16(aL + (ar0 * APITCH + ac0) * 2, Wlo + (size_t)(m0 + ar0) * CC + k0 + ac0); \
        cp_async16(aL + (ar1 * APITCH + ac1) * 2, Wlo + (size_t)(m0 + ar1) * CC + k0 + ac1); \
        cp_async16(bH + (br0 * BPITCH + bc0) * 2, Xhi + (size_t)(k0 + br0) * HW + n0 + bc0); \
        cp_async16(bH + (br1 * BPITCH + bc1) * 2, Xhi + (size_t)(k0 + br1) * HW + n0 + bc1); \
        cp_async16(bL + (br0 * BPITCH + bc0) * 2, Xlo + (size_t)(k0 + br0) * HW + n0 + bc0); \
        cp_async16(bL + (br1 * BPITCH + bc1) * 2, Xlo + (size_t)(k0 + br1) * HW + n0 + bc1); \
        asm volatile("cp.async.commit_group;");                                   \
    } while (0)

    LOAD_TILE(0, 0);
    for (int it = 0; it < NT; ++it) {
        if (it + 1 < NT) { LOAD_TILE(it + 1, (it + 1) & 1); asm volatile("cp.async.wait_group 1;"); }
        else             { asm volatile("cp.async.wait_group 0;"); }
        __syncthreads();

        const int buf = it & 1;
        const uint32_t aH = base + oAH + buf * CSTG_A, aL = base + oAL + buf * CSTG_A;
        const uint32_t bH = base + oBH + buf * CSTG_B, bL = base + oBL + buf * CSTG_B;
#pragma unroll
        for (int kk = 0; kk < 32; kk += 16) {
            uint32_t ah[4][4], al[4][4], bh[2][4], bl[2][4];
#pragma unroll
            for (int im = 0; im < 4; im++) {
                uint32_t off = (((wm + im * 16 + (lane & 15)) * APITCH) + kk + ((lane >> 4) << 3)) * 2;
                ldsm_x4(ah[im][0], ah[im][1], ah[im][2], ah[im][3], aH + off);
                ldsm_x4(al[im][0], al[im][1], al[im][2], al[im][3], aL + off);
            }
#pragma unroll
            for (int jn = 0; jn < 2; jn++) {
                uint32_t off = (((kk + (lane & 7) + ((lane >> 3) & 1) * 8) * BPITCH)
                                + wn + jn * 16 + ((lane >> 4) << 3)) * 2;
                ldsm_x4_t(bh[jn][0], bh[jn][1], bh[jn][2], bh[jn][3], bH + off);
                ldsm_x4_t(bl[jn][0], bl[jn][1], bl[jn][2], bl[jn][3], bL + off);
            }
#pragma unroll
            for (int im = 0; im < 4; im++)
#pragma unroll
                for (int jn = 0; jn < 2; jn++) {
                    mma_bf16(acc[im][jn * 2 + 0], ah[im], bh[jn][0], bh[jn][1]);
                    mma_bf16(acc[im][jn * 2 + 1], ah[im], bh[jn][2], bh[jn][3]);
                }
#pragma unroll
            for (int im = 0; im < 4; im++)
#pragma unroll
                for (int jn = 0; jn < 2; jn++) {
                    mma_bf16(acc[im][jn * 2 + 0], al[im], bh[jn][0], bh[jn][1]);
                    mma_bf16(acc[im][jn * 2 + 1], al[im], bh[jn][2], bh[jn][3]);
                }
#pragma unroll
            for (int im = 0; im < 4; im++)
#pragma unroll
                for (int jn = 0; jn < 2; jn++) {
                    mma_bf16(acc[im][jn * 2 + 0], ah[im], bl[jn][0], bl[jn][1]);
                    mma_bf16(acc[im][jn * 2 + 1], ah[im], bl[jn][2], bl[jn][3]);
                }
        }
        __syncthreads();
    }
#undef LOAD_TILE

    if (sel == 0) {
        __nv_bfloat16* Oh = g_xfhi + (size_t)b * CC * HW;
        __nv_bfloat16* Ol = g_xflo + (size_t)b * CC * HW;
#pragma unroll
        for (int im = 0; im < 4; im++) {
            int row = m0 + wm + im * 16 + (lane >> 2);
            float bv0 = bias[row], bv1 = bias[row + 8];
#pragma unroll
            for (int j8 = 0; j8 < 4; j8++) {
                int col = n0 + wn + j8 * 8 + (lane & 3) * 2;
                __nv_bfloat16 h0, h1, h2, h3, l0, l1, l2, l3;
                split_val(acc[im][j8][0] + bv0, h0, l0);
                split_val(acc[im][j8][1] + bv0, h1, l1);
                split_val(acc[im][j8][2] + bv1, h2, l2);
                split_val(acc[im][j8][3] + bv1, h3, l3);
                *reinterpret_cast<__nv_bfloat162*>(&Oh[(size_t)row * HW + col]) = __nv_bfloat162{h0, h1};
                *reinterpret_cast<__nv_bfloat162*>(&Ol[(size_t)row * HW + col]) = __nv_bfloat162{l0, l1};
                *reinterpret_cast<__nv_bfloat162*>(&Oh[(size_t)(row + 8) * HW + col]) = __nv_bfloat162{h2, h3};
                *reinterpret_cast<__nv_bfloat162*>(&Ol[(size_t)(row + 8) * HW + col]) = __nv_bfloat162{l2, l3};
            }
        }
    } else {
        float* Yb = g_buf1 + (size_t)b * CC * HW;
        float* psum = g_mu_part;
        float* psq  = g_mu_part + (size_t)BN_SLOTS * CC;
        const int slot = ((b * 32 + blockIdx.x) * 4) + (wid >> 1);
#pragma unroll
        for (int im = 0; im < 4; im++) {
            int row = m0 + wm + im * 16 + (lane >> 2);
            float s0 = 0.f, q0 = 0.f, s1 = 0.f, q1 = 0.f;
#pragma unroll
            for (int j8 = 0; j8 < 4; j8++) {
                int col = n0 + wn + j8 * 8 + (lane & 3) * 2;
                float a0 = acc[im][j8][0], a1 = acc[im][j8][1];
                float a2 = acc[im][j8][2], a3 = acc[im][j8][3];
                *reinterpret_cast<float2*>(&Yb[(size_t)row * HW + col]) = {a0, a1};
                *reinterpret_cast<float2*>(&Yb[(size_t)(row + 8) * HW + col]) = {a2, a3};
                s0 += a0 + a1; q0 = fmaf(a0, a0, fmaf(a1, a1, q0));
                s1 += a2 + a3; q1 = fmaf(a2, a2, fmaf(a3, a3, q1));
            }
            s0 += __shfl_xor_sync(0xffffffffu, s0, 1); s0 += __shfl_xor_sync(0xffffffffu, s0, 2);
            q0 += __shfl_xor_sync(0xffffffffu, q0, 1); q0 += __shfl_xor_sync(0xffffffffu, q0, 2);
            s1 += __shfl_xor_sync(0xffffffffu, s1, 1); s1 += __shfl_xor_sync(0xffffffffu, s1, 2);
            q1 += __shfl_xor_sync(0xffffffffu, q1, 1); q1 += __shfl_xor_sync(0xffffffffu, q1, 2);
            if ((lane & 3) == 0) {
                psum[(size_t)slot * CC + row]     = s0;
                psq [(size_t)slot * CC + row]     = q0;
                psum[(size_t)slot * CC + row + 8] = s1;
                psq [(size_t)slot * CC + row + 8] = q1;
            }
        }
    }
}

// ---------------------------------------------------------------------------
// BN finalize
// ---------------------------------------------------------------------------
__global__ void bn_final_kernel(const float* __restrict__ gamma,
                                const float* __restrict__ beta) {
    const int o = blockIdx.x;
    const int tid = threadIdx.x;
    const float* psum = g_mu_part;
    const float* psq  = g_mu_part + (size_t)BN_SLOTS * CC;
    float s = 0.f, q = 0.f;
    for (int i = tid; i < BN_SLOTS; i += 256) {
        s += psum[(size_t)i * CC + o];
        q += psq [(size_t)i * CC + o];
    }
    __shared__ float r1[256], r2[256];
    r1[tid] = s; r2[tid] = q; __syncthreads();
    for (int st = 128; st > 0; st >>= 1) {
        if (tid < st) { r1[tid] += r1[tid + st]; r2[tid] += r2[tid + st]; }
        __syncthreads();
    }
    if (tid == 0) {
        const float invM = 1.f / (float)(BB * HW);
        float mean = r1[0] * invM;
        float var  = r2[0] * invM - mean * mean;
        float sc = gamma[o] * rsqrtf(var + 1e-5f);
        g_scale[o] = sc;
        g_shift[o] = beta[o] - mean * sc;
    }
}

// ---------------------------------------------------------------------------
// E-step, M-tile 256, fused 3-term, staggered kk (R15 exact)
// ---------------------------------------------------------------------------
#define EAP 264
#define ESTG_A (32 * EAP * 2)
#define ESTG_B (32 * 72 * 2)
#define EBP 72
#define ESTEP_SMEM (4 * ESTG_A + 4 * ESTG_B)
__global__ __launch_bounds__(256) void estep_mma_kernel() {
    extern __shared__ __align__(16) char esm[];
    const int b  = blockIdx.y;
    const int n0 = blockIdx.x * 256;
    const int tid  = threadIdx.x;
    const int lane = tid & 31;
    const int wid  = tid >> 5;
    const int wm   = (wid & 3) * 64;
    const int wn   = (wid >> 2) * 32;
    const int kk0  = (wid & 1) << 4;

    const uint32_t base = smem_u32(esm);
    const uint32_t oAH = 0, oAL = 2 * ESTG_A;
    const uint32_t oBH = 4 * ESTG_A, oBL = 4 * ESTG_A + 2 * ESTG_B;
    float* L = (float*)esm;

    const __nv_bfloat16* Xh = g_xfhi + (size_t)b * CC * HW;
    const __nv_bfloat16* Xl = g_xflo + (size_t)b * CC * HW;
    const __nv_bfloat16* Mh = g_muhi + (size_t)b * CC * KK;
    const __nv_bfloat16* Ml = g_mulo + (size_t)b * CC * KK;

    float acc[4][4][4];
#pragma unroll
    for (int i = 0; i < 4; i++)
#pragma unroll
        for (int j = 0; j < 4; j++)
#pragma unroll
            for (int q = 0; q < 4; q++) acc[i][j][q] = 0.f;

    const int brow = tid >> 3, bcol = (tid & 7) * 8;

    const int NT = 16;
#define LOAD_TILE(IT, BUF) do {                                                   \
        int k0 = (IT) * 32;                                                       \
        uint32_t aH = base + oAH + (BUF) * ESTG_A, aL = base + oAL + (BUF) * ESTG_A; \
        uint32_t bH = base + oBH + (BUF) * ESTG_B, bL = base + oBL + (BUF) * ESTG_B; \
        _Pragma("unroll")                                                          \
        for (int t = 0; t < 4; t++) {                                             \
            int idx = tid + t * 256, r = idx >> 5, c = (idx & 31) * 8;            \
            cp_async16(aH + (r * EAP + c) * 2, Xh + (size_t)(k0 + r) * HW + n0 + c); \
            cp_async16(aL + (r * EAP + c) * 2, Xl + (size_t)(k0 + r) * HW + n0 + c); \
        }                                                                          \
        cp_async16(bH + (brow * EBP + bcol) * 2, Mh + (size_t)(k0 + brow) * KK + bcol); \
        cp_async16(bL + (brow * EBP + bcol) * 2, Ml + (size_t)(k0 + brow) * KK + bcol); \
        asm volatile("cp.async.commit_group;");                                   \
    } while (0)

    LOAD_TILE(0, 0);
    for (int it = 0; it < NT; ++it) {
        if (it + 1 < NT) { LOAD_TILE(it + 1, (it + 1) & 1); asm volatile("cp.async.wait_group 1;"); }
        else             { asm volatile("cp.async.wait_group 0;"); }
        __syncthreads();

        const int buf = it & 1;
        const uint32_t aH = base + oAH + buf * ESTG_A, aL = base + oAL + buf * ESTG_A;
        const uint32_t bH = base + oBH + buf * ESTG_B, bL = base + oBL + buf * ESTG_B;
#pragma unroll
        for (int t = 0; t < 2; t++) {
            const int kk = kk0 ^ (t << 4);
            uint32_t ah[4][4], al[4][4], bh[2][4], bl[2][4];
#pragma unroll
            for (int f = 0; f < 4; f++) {
                uint32_t off = (((kk + (lane & 7) + ((lane >> 4) << 3)) * EAP)
                                + wm + f * 16 + ((lane >> 3) & 1) * 8) * 2;
                ldsm_x4_t(ah[f][0], ah[f][1], ah[f][2], ah[f][3], aH + off);
                ldsm_x4_t(al[f][0], al[f][1], al[f][2], al[f][3], aL + off);
            }
#pragma unroll
            for (int jn = 0; jn < 2; jn++) {
                uint32_t off = (((kk + (lane & 7) + ((lane >> 3) & 1) * 8) * EBP)
                                + wn + jn * 16 + ((lane >> 4) << 3)) * 2;
                ldsm_x4_t(bh[jn][0], bh[jn][1], bh[jn][2], bh[jn][3], bH + off);
                ldsm_x4_t(bl[jn][0], bl[jn][1], bl[jn][2], bl[jn][3], bL + off);
            }
#pragma unroll
            for (int f = 0; f < 4; f++)
#pragma unroll
                for (int jn = 0; jn < 2; jn++) {
                    mma_bf16(acc[f][jn * 2 + 0], ah[f], bh[jn][0], bh[jn][1]);
                    mma_bf16(acc[f][jn * 2 + 1], ah[f], bh[jn][2], bh[jn][3]);
                }
#pragma unroll
            for (int f = 0; f < 4; f++)
#pragma unroll
                for (int jn = 0; jn < 2; jn++) {
                    mma_bf16(acc[f][jn * 2 + 0], al[f], bh[jn][0], bh[jn][1]);
                    mma_bf16(acc[f][jn * 2 + 1], al[f], bh[jn][2], bh[jn][3]);
                }
#pragma unroll
            for (int f = 0; f < 4; f++)
#pragma unroll
                for (int jn = 0; jn < 2; jn++) {
                    mma_bf16(acc[f][jn * 2 + 0], ah[f], bl[jn][0], bl[jn][1]);
                    mma_bf16(acc[f][jn * 2 + 1], ah[f], bl[jn][2], bl[jn][3]);
                }
        }
        __syncthreads();
    }
#undef LOAD_TILE

#pragma unroll
    for (int f = 0; f < 4; f++) {
        int row = wm + f * 16 + (lane >> 2);
#pragma unroll
        for (int j8 = 0; j8 < 4; j8++) {
            int col = wn + j8 * 8 + (lane & 3) * 2;
            *reinterpret_cast<float2*>(&L[row * 68 + col])       = {acc[f][j8][0], acc[f][j8][1]};
            *reinterpret_cast<float2*>(&L[(row + 8) * 68 + col]) = {acc[f][j8][2], acc[f][j8][3]};
        }
    }
    __syncthreads();

    for (int i = 0; i < 32; i++) {
        int r = wid * 32 + i;
        float v0 = L[r * 68 + lane], v1 = L[r * 68 + lane + 32];
        float m = fmaxf(v0, v1);
#pragma unroll
        for (int off = 16; off > 0; off >>= 1)
            m = fmaxf(m, __shfl_xor_sync(0xffffffffu, m, off));
        float e0 = expf(v0 - m), e1 = expf(v1 - m);
        float s = e0 + e1;
#pragma unroll
        for (int off = 16; off > 0; off >>= 1)
            s += __shfl_xor_sync(0xffffffffu, s, off);
        float inv = 1.f / s;
        float z0 = e0 * inv, z1 = e1 * inv;
        size_t zbase = (size_t)b * HW * KK + (size_t)(n0 + r) * KK;
        __nv_bfloat16 h, l;
        split_val(z0, h, l); g_zhi[zbase + lane] = h;      g_zlo[zbase + lane] = l;
        split_val(z1, h, l); g_zhi[zbase + lane + 32] = h; g_zlo[zbase + lane + 32] = l;
    }
}

// ---------------------------------------------------------------------------
// M-step, M-tile 256, fused 3-term, staggered kk (R15 exact)
// ---------------------------------------------------------------------------
#define MAP 40
#define MBP 72
#define MSTG_A (256 * MAP * 2)
#define MSTG_B (32 * MBP * 2)
#define MSTEP_SMEM (4 * MSTG_A + 4 * MSTG_B)
__global__ __launch_bounds__(256) void mstep_mma_kernel() {
    extern __shared__ __align__(16) char msm[];
    const int b  = blockIdx.z;
    const int s  = blockIdx.y;
    const int c0 = blockIdx.x * 256;
    const int tid  = threadIdx.x;
    const int lane = tid & 31;
    const int wid  = tid >> 5;
    const int wm   = (wid & 3) * 64;
    const int wn   = (wid >> 2) * 32;
    const int kk0  = (wid & 1) << 4;

    const uint32_t base = smem_u32(msm);
    const uint32_t oAH = 0, oAL = 2 * MSTG_A;
    const uint32_t oBH = 4 * MSTG_A, oBL = 4 * MSTG_A + 2 * MSTG_B;

    const __nv_bfloat16* Xh = g_xfhi + (size_t)b * CC * HW;
    const __nv_bfloat16* Xl = g_xflo + (size_t)b * CC * HW;
    const __nv_bfloat16* Zh = g_zhi  + (size_t)b * HW * KK;
    const __nv_bfloat16* Zl = g_zlo  + (size_t)b * HW * KK;

    float acc[4][4][4];
#pragma unroll
    for (int i = 0; i < 4; i++)
#pragma unroll
        for (int j = 0; j < 4; j++)
#pragma unroll
            for (int q = 0; q < 4; q++) acc[i][j][q] = 0.f;

    const int brow = tid >> 3, bcol = (tid & 7) * 8;

    const int nbeg = s * (HW / SPLIT);
    const int NT = 16;
#define LOAD_TILE(IT, BUF) do {                                                   \
        int n0 = nbeg + (IT) * 32;                                                \
        uint32_t aH = base + oAH + (BUF) * MSTG_A, aL = base + oAL + (BUF) * MSTG_A; \
        uint32_t bH = base + oBH + (BUF) * MSTG_B, bL = base + oBL + (BUF) * MSTG_B; \
        _Pragma("unroll")                                                          \
        for (int t = 0; t < 4; t++) {                                             \
            int idx = tid + t * 256, r = idx >> 2, c = (idx & 3) * 8;             \
            cp_async16(aH + (r * MAP + c) * 2, Xh + (size_t)(c0 + r) * HW + n0 + c); \
            cp_async16(aL + (r * MAP + c) * 2, Xl + (size_t)(c0 + r) * HW + n0 + c); \
        }                                                                          \
        cp_async16(bH + (brow * MBP + bcol) * 2, Zh + (size_t)(n0 + brow) * KK + bcol); \
        cp_async16(bL + (brow * MBP + bcol) * 2, Zl + (size_t)(n0 + brow) * KK + bcol); \
        asm volatile("cp.async.commit_group;");                                   \
    } while (0)

    LOAD_TILE(0, 0);
    for (int it = 0; it < NT; ++it) {
        if (it + 1 < NT) { LOAD_TILE(it + 1, (it + 1) & 1); asm volatile("cp.async.wait_group 1;"); }
        else             { asm volatile("cp.async.wait_group 0;"); }
        __syncthreads();

        const int buf = it & 1;
        const uint32_t aH = base + oAH + buf * MSTG_A, aL = base + oAL + buf * MSTG_A;
        const uint32_t bH = base + oBH + buf * MSTG_B, bL = base + oBL + buf * MSTG_B;
#pragma unroll
        for (int t = 0; t < 2; t++) {
            const int kk = kk0 ^ (t << 4);
            uint32_t ah[4][4], al[4][4], bh[2][4], bl[2][4];
#pragma unroll
            for (int im = 0; im < 4; im++) {
                uint32_t off = (((wm + im * 16 + (lane & 15)) * MAP) + kk + ((lane >> 4) << 3)) * 2;
                ldsm_x4(ah[im][0], ah[im][1], ah[im][2], ah[im][3], aH + off);
                ldsm_x4(al[im][0], al[im][1], al[im][2], al[im][3], aL + off);
            }
#pragma unroll
            for (int jn = 0; jn < 2; jn++) {
                uint32_t off = (((kk + (lane & 7) + ((lane >> 3) & 1) * 8) * MBP)
                                + wn + jn * 16 + ((lane >> 4) << 3)) * 2;
                ldsm_x4_t(bh[jn][0], bh[jn][1], bh[jn][2], bh[jn][3], bH + off);
                ldsm_x4_t(bl[jn][0], bl[jn][1], bl[jn][2], bl[jn][3], bL + off);
            }
#pragma unroll
            for (int im = 0; im < 4; im++)
#pragma unroll
                for (int jn = 0; jn < 2; jn++) {
                    mma_bf16(acc[im][jn * 2 + 0], ah[im], bh[jn][0], bh[jn][1]);
                    mma_bf16(acc[im][jn * 2 + 1], ah[im], bh[jn][2], bh[jn][3]);
                }
#pragma unroll
            for (int im = 0; im < 4; im++)
#pragma unroll
                for (int jn = 0; jn < 2; jn++) {
                    mma_bf16(acc[im][jn * 2 + 0], al[im], bh[jn][0], bh[jn][1]);
                    mma_bf16(acc[im][jn * 2 + 1], al[im], bh[jn][2], bh[jn][3]);
                }
#pragma unroll
            for (int im = 0; im < 4; im++)
#pragma unroll
                for (int jn = 0; jn < 2; jn++) {
                    mma_bf16(acc[im][jn * 2 + 0], ah[im], bl[jn][0], bl[jn][1]);
                    mma_bf16(acc[im][jn * 2 + 1], ah[im], bl[jn][2], bl[jn][3]);
                }
        }
        __syncthreads();
    }
#undef LOAD_TILE

    float* outp = g_mu_part + ((size_t)b * SPLIT + s) * CC * KK;
#pragma unroll
    for (int im = 0; im < 4; im++) {
        int row = c0 + wm + im * 16 + (lane >> 2);
#pragma unroll
        for (int j8 = 0; j8 < 4; j8++) {
            int col = wn + j8 * 8 + (lane & 3) * 2;
            *reinterpret_cast<float2*>(&outp[(size_t)row * KK + col])       = {acc[im][j8][0], acc[im][j8][1]};
            *reinterpret_cast<float2*>(&outp[(size_t)(row + 8) * KK + col]) = {acc[im][j8][2], acc[im][j8][3]};
        }
    }
}

// ---------------------------------------------------------------------------
// Reduce split-K partials + l2-normalize (register-resident scratch: each
// thread owns channels c = tid + {0,128,256,384})
// ---------------------------------------------------------------------------
__global__ void reduce_l2norm_kernel(float* __restrict__ out_mu) {
    const int bk = blockIdx.x;
    const int b = bk >> 6, k = bk & 63;
    const int tid = threadIdx.x;

    const float* part = g_mu_part + (size_t)b * SPLIT * CC * KK;

    float vloc[4];
    float s2 = 0.f;
#pragma unroll
    for (int j = 0; j < 4; j++) {
        int c = tid + j * 128;
        float v = 0.f;
#pragma unroll
        for (int s = 0; s < SPLIT; s++)
            v += part[(size_t)s * CC * KK + (size_t)c * KK + k];
        vloc[j] = v;
        s2 += v * v;
    }
    __shared__ float red[128];
    red[tid] = s2; __syncthreads();
    for (int st = 64; st > 0; st >>= 1) {
        if (tid < st) red[tid] += red[tid + st];
        __syncthreads();
    }
    float scale = 1.f / (1e-6f + sqrtf(red[0]));
#pragma unroll
    for (int j = 0; j < 4; j++) {
        int c = tid + j * 128;
        size_t idx = (size_t)b * CC * KK + (size_t)c * KK + k;
        float v = vloc[j] * scale;
        __nv_bfloat16 h, l; split_val(v, h, l);
        g_muhi[idx] = h; g_mulo[idx] = l;
        if (out_mu) out_mu[idx] = v;
    }
}

// ---------------------------------------------------------------------------
// Reconstruction (unchanged)
// ---------------------------------------------------------------------------
#define RP 40
#define PIPE_WAIT_SYNC(IT, NT)                                   \
    if ((IT) + 2 < (NT)) { asm volatile("cp.async.wait_group 1;"); } \
    else                 { asm volatile("cp.async.wait_group 0;"); } \
    __syncthreads();

__global__ __launch_bounds__(256) void recon_mma_kernel() {
    const int b  = blockIdx.z;
    const int c0 = blockIdx.y * 128;
    const int n0 = blockIdx.x * 128;
    const int tid  = threadIdx.x;
    const int lane = tid & 31;
    const int wid  = tid >> 5;
    const int wm   = (wid & 1) * 64;
    const int wn   = (wid >> 1) * 32;

    __shared__ __nv_bfloat16 As[3][128 * RP];
    __shared__ __nv_bfloat16 Bs[3][128 * RP];

    const __nv_bfloat16* Mh = g_muhi + (size_t)b * CC * KK;
    const __nv_bfloat16* Ml = g_mulo + (size_t)b * CC * KK;
    const __nv_bfloat16* Zh = g_zhi  + (size_t)b * HW * KK;
    const __nv_bfloat16* Zl = g_zlo  + (size_t)b * HW * KK;

    float acc[4][4][4];
#pragma unroll
    for (int i = 0; i < 4; i++)
#pragma unroll
        for (int j = 0; j < 4; j++)
#pragma unroll
            for (int q = 0; q < 4; q++) acc[i][j][q] = 0.f;

    const uint32_t sA0 = smem_u32(As[0]);
    const uint32_t sB0 = smem_u32(Bs[0]);
    const uint32_t ssz = 128 * RP * 2;

    const int aq0 = tid, aq1 = tid + 256;
    const int ar0 = aq0 >> 2, ac0 = (aq0 & 3) * 8;
    const int ar1 = aq1 >> 2, ac1 = (aq1 & 3) * 8;

    const int NT = 6;
#define LOAD_TILE(IT, BUF) do {                                                   \
        int pass = (IT) >> 1, k0 = ((IT) & 1) * 32;                               \
        const __nv_bfloat16* Ap = (pass == 1) ? Ml : Mh;                          \
        const __nv_bfloat16* Bp = (pass == 2) ? Zl : Zh;                          \
        uint32_t sa = sA0 + (BUF) * ssz, sb = sB0 + (BUF) * ssz;                  \
        cp_async16(sa + (ar0 * RP + ac0) * 2, Ap + (size_t)(c0 + ar0) * KK + k0 + ac0); \
        cp_async16(sa + (ar1 * RP + ac1) * 2, Ap + (size_t)(c0 + ar1) * KK + k0 + ac1); \
        cp_async16(sb + (ar0 * RP + ac0) * 2, Bp + (size_t)(n0 + ar0) * KK + k0 + ac0); \
        cp_async16(sb + (ar1 * RP + ac1) * 2, Bp + (size_t)(n0 + ar1) * KK + k0 + ac1); \
        asm volatile("cp.async.commit_group;");                                   \
    } while (0)

    LOAD_TILE(0, 0);
    LOAD_TILE(1, 1);
    int buf = 0;
    for (int it = 0; it < NT; ++it) {
        PIPE_WAIT_SYNC(it, NT);
        if (it + 2 < NT) {
            int nb = buf + 2; if (nb >= 3) nb -= 3;
            LOAD_TILE(it + 2, nb);
        }
        const uint32_t sa = sA0 + buf * ssz;
        const uint32_t sb = sB0 + buf * ssz;
#pragma unroll
        for (int kk = 0; kk < 32; kk += 16) {
            uint32_t a[4][4], bfr[2][4];
#pragma unroll
            for (int im = 0; im < 4; im++) {
                uint32_t addr = sa + (((wm + im * 16 + (lane & 15)) * RP) + kk + ((lane >> 4) << 3)) * 2;
                ldsm_x4(a[im][0], a[im][1], a[im][2], a[im][3], addr);
            }
#pragma unroll
            for (int jn = 0; jn < 2; jn++) {
                uint32_t addr = sb + (((wn + jn * 16 + (lane & 7) + ((lane >> 4) << 3)) * RP)
                                      + kk + ((lane >> 3) & 1) * 8) * 2;
                ldsm_x4(bfr[jn][0], bfr[jn][1], bfr[jn][2], bfr[jn][3], addr);
            }
#pragma unroll
            for (int im = 0; im < 4; im++)
#pragma unroll
                for (int jn = 0; jn < 2; jn++) {
                    mma_bf16(acc[im][jn * 2 + 0], a[im], bfr[jn][0], bfr[jn][1]);
                    mma_bf16(acc[im][jn * 2 + 1], a[im], bfr[jn][2], bfr[jn][3]);
                }
        }
        if (++buf == 3) buf = 0;
    }
#undef LOAD_TILE

    __nv_bfloat16* Oh = g_xrhi + (size_t)b * CC * HW;
    __nv_bfloat16* Ol = g_xrlo + (size_t)b * CC * HW;
#pragma unroll
    for (int im = 0; im < 4; im++) {
        int row = c0 + wm + im * 16 + (lane >> 2);
#pragma unroll
        for (int j8 = 0; j8 < 4; j8++) {
            int col = n0 + wn + j8 * 8 + (lane & 3) * 2;
            __nv_bfloat16 h0, h1, h2, h3, l0, l1, l2, l3;
            split_val(fmaxf(acc[im][j8][0], 0.f), h0, l0);
            split_val(fmaxf(acc[im][j8][1], 0.f), h1, l1);
            split_val(fmaxf(acc[im][j8][2], 0.f), h2, l2);
            split_val(fmaxf(acc[im][j8][3], 0.f), h3, l3);
            *reinterpret_cast<__nv_bfloat162*>(&Oh[(size_t)row * HW + col]) = __nv_bfloat162{h0, h1};
            *reinterpret_cast<__nv_bfloat162*>(&Ol[(size_t)row * HW + col]) = __nv_bfloat162{l0, l1};
            *reinterpret_cast<__nv_bfloat162*>(&Oh[(size_t)(row + 8) * HW + col]) = __nv_bfloat162{h2, h3};
            *reinterpret_cast<__nv_bfloat162*>(&Ol[(size_t)(row + 8) * HW + col]) = __nv_bfloat162{l2, l3};
        }
    }
}

// ---------------------------------------------------------------------------
// final / z-transpose (zt reconstructs z = hi + lo from splits)
// ---------------------------------------------------------------------------
__global__ void final_kernel(const float* __restrict__ x, float* __restrict__ out) {
    const int b = blockIdx.z, o = blockIdx.y;
    const size_t base = (size_t)b * CC * HW + (size_t)o * HW
                      + (size_t)blockIdx.x * 1024 + (size_t)threadIdx.x * 4;
    const float sc = g_scale[o], sh = g_shift[o];
    float4 v2 = *reinterpret_cast<const float4*>(&g_buf1[base]);
    float4 vx = *reinterpret_cast<const float4*>(&x[base]);
    float4 r;
    r.x = fmaxf(fmaf(v2.x, sc, sh) + vx.x, 0.f);
    r.y = fmaxf(fmaf(v2.y, sc, sh) + vx.y, 0.f);
    r.z = fmaxf(fmaf(v2.z, sc, sh) + vx.z, 0.f);
    r.w = fmaxf(fmaf(v2.w, sc, sh) + vx.w, 0.f);
    *reinterpret_cast<float4*>(&out[base]) = r;
}

__global__ void zt_kernel(float* __restrict__ zt) {
    const int b  = blockIdx.z;
    const int n0 = blockIdx.x * 32;
    const int k0 = blockIdx.y * 32;
    __shared__ float t[32][33];
    const int tx = threadIdx.x, ty = threadIdx.y;
    const __nv_bfloat16* zh = g_zhi + (size_t)b * HW * KK;
    const __nv_bfloat16* zl = g_zlo + (size_t)b * HW * KK;
#pragma unroll
    for (int c = 0; c < 32; c += 8) {
        size_t idx = (size_t)(n0 + ty + c) * KK + k0 + tx;
        t[ty + c][tx] = __bfloat162float(zh[idx]) + __bfloat162float(zl[idx]);
    }
    __syncthreads();
    float* ztb = zt + (size_t)b * KK * HW;
#pragma unroll
    for (int c = 0; c < 32; c += 8)
        ztb[(size_t)(k0 + ty + c) * HW + n0 + tx] = t[tx][ty + c];
}

// ---------------------------------------------------------------------------
// Launch
// ---------------------------------------------------------------------------
extern "C" void kernel_launch(void* const* d_in, const int* in_sizes, int n_in,
                              void* d_out, int out_size) {
    const float* x     = (const float*)d_in[0];
    const float* w1    = (const float*)d_in[1];
    const float* b1    = (const float*)d_in[2];
    const float* w2    = (const float*)d_in[3];
    const float* gamma = (const float*)d_in[4];
    const float* beta  = (const float*)d_in[5];
    const float* mu_in = (const float*)d_in[6];

    float* out    = (float*)d_out;
    float* out_mu = out + (size_t)BB * CC * HW;
    float* out_zt = out_mu + (size_t)BB * CC * KK;

    static int smem_set = 0;
    if (!smem_set) {
        cudaFuncSetAttribute(conv_mma_kernel,  cudaFuncAttributeMaxDynamicSharedMemorySize, CONV_SMEM);
        cudaFuncSetAttribute(estep_mma_kernel, cudaFuncAttributeMaxDynamicSharedMemorySize, ESTEP_SMEM);
        cudaFuncSetAttribute(mstep_mma_kernel, cudaFuncAttributeMaxDynamicSharedMemorySize, MSTEP_SMEM);
        smem_set = 1;
    }

    prologue_kernel<<<NXB + NWB + NMB * BB, 256>>>(x, w1, w2, mu_in);

    conv_mma_kernel<<<dim3(HW / 128, CC / 128, BB), 256, CONV_SMEM>>>(b1, 0);

    for (int s = 0; s < 3; s++) {
        estep_mma_kernel<<<dim3(HW / 256, BB), 256, ESTEP_SMEM>>>();
        mstep_mma_kernel<<<dim3(CC / 256, SPLIT, BB), 256, MSTEP_SMEM>>>();
        reduce_l2norm_kernel<<<BB * KK, 128>>>(s == 2 ? out_mu : nullptr);
    }

    recon_mma_kernel<<<dim3(HW / 128, CC / 128, BB), 256>>>();

    conv_mma_kernel<<<dim3(HW / 128, CC / 128, BB), 256, CONV_SMEM>>>(nullptr, 1);

    bn_final_kernel<<<CC, 256>>>(gamma, beta);
    final_kernel<<<dim3(HW / 1024, CC, BB), 256>>>(x, out);
    zt_kernel<<<dim3(HW / 32, KK / 32, BB), dim3(32, 8)>>>(out_zt);
}